// round 11
// baseline (speedup 1.0000x reference)
#include <cuda_runtime.h>
#include <cuda_bf16.h>
#include <math.h>
#include <stdint.h>

// Problem constants
#define BB   16
#define SS   512
#define HH   768
#define II   3072
#define NHH  12
#define DHH  64
#define LL   6
#define M0   (BB*SS)       // 8192 tokens
#define NBA  (BB*NHH)      // 192 attention batches
#define H3   (3*HH)        // 2304

// ---------------------------------------------------------------------------
// Scratch buffers (activations as bf16 hi/lo pairs; T fp32 for LayerNorm)
// ---------------------------------------------------------------------------
__device__ __nv_bfloat16 g_XH[M0*HH],   g_XL[M0*HH];
__device__ __nv_bfloat16 g_QKVH[M0*H3], g_QKVL[M0*H3];
__device__ __nv_bfloat16 g_CH[M0*HH],   g_CL[M0*HH];
__device__ __nv_bfloat16 g_AH[M0*HH],   g_AL[M0*HH];
__device__ __nv_bfloat16 g_IH[M0*II],   g_IL[M0*II];
__device__ float g_T[M0*HH];
// pre-split bf16 weights (hi/lo), original [K][N] layout
__device__ __nv_bfloat16 g_WqkvH[LL*HH*H3], g_WqkvL[LL*HH*H3];
__device__ __nv_bfloat16 g_WoH[LL*HH*HH],   g_WoL[LL*HH*HH];
__device__ __nv_bfloat16 g_WiH[LL*HH*II],   g_WiL[LL*HH*II];
__device__ __nv_bfloat16 g_Wo2H[LL*II*HH],  g_Wo2L[LL*II*HH];
__device__ float g_bqkv[LL*H3];

// ---------------------------------------------------------------------------
// PTX helpers
// ---------------------------------------------------------------------------
__device__ __forceinline__ uint32_t smem_u32(const void* p) {
    return (uint32_t)__cvta_generic_to_shared(p);
}
__device__ __forceinline__ void ldsm_x4(uint32_t* r, uint32_t a) {
    asm volatile("ldmatrix.sync.aligned.m8n8.x4.shared.b16 {%0,%1,%2,%3}, [%4];"
        : "=r"(r[0]), "=r"(r[1]), "=r"(r[2]), "=r"(r[3]) : "r"(a));
}
__device__ __forceinline__ void ldsm_x4t(uint32_t* r, uint32_t a) {
    asm volatile("ldmatrix.sync.aligned.m8n8.x4.trans.shared.b16 {%0,%1,%2,%3}, [%4];"
        : "=r"(r[0]), "=r"(r[1]), "=r"(r[2]), "=r"(r[3]) : "r"(a));
}
__device__ __forceinline__ void mma16816(float* c, const uint32_t* a, const uint32_t* b) {
    asm volatile(
        "mma.sync.aligned.m16n8k16.row.col.f32.bf16.bf16.f32 "
        "{%0,%1,%2,%3}, {%4,%5,%6,%7}, {%8,%9}, {%0,%1,%2,%3};"
        : "+f"(c[0]), "+f"(c[1]), "+f"(c[2]), "+f"(c[3])
        : "r"(a[0]), "r"(a[1]), "r"(a[2]), "r"(a[3]), "r"(b[0]), "r"(b[1]));
}
#define CP_ASYNC16(dst, src) \
    asm volatile("cp.async.cg.shared.global [%0], [%1], 16;" :: "r"(dst), "l"(src) : "memory")
#define CP_COMMIT() asm volatile("cp.async.commit_group;" ::: "memory")
#define CP_WAIT1()  asm volatile("cp.async.wait_group 1;" ::: "memory")

// fp32 -> (bf16 hi, bf16 lo) exact-residual split
__device__ __forceinline__ void split1(float x, unsigned short& hi, unsigned short& lo) {
    __nv_bfloat16 h = __float2bfloat16(x);
    hi = *reinterpret_cast<unsigned short*>(&h);
    float r = x - __bfloat162float(h);
    __nv_bfloat16 l = __float2bfloat16(r);
    lo = *reinterpret_cast<unsigned short*>(&l);
}
__device__ __forceinline__ void split4(float4 v, ushort4& hi, ushort4& lo) {
    split1(v.x, hi.x, lo.x);
    split1(v.y, hi.y, lo.y);
    split1(v.z, hi.z, lo.z);
    split1(v.w, hi.w, lo.w);
}
__device__ __forceinline__ float bf2f(unsigned short u) {
    __nv_bfloat16 h = *reinterpret_cast<__nv_bfloat16*>(&u);
    return __bfloat162float(h);
}

// ---------------------------------------------------------------------------
// Preprocessing: ALL weight splits in ONE launch (blockIdx.z selects matrix)
// ---------------------------------------------------------------------------
__global__ void split_all(const float* __restrict__ Wq, const float* __restrict__ Wk,
                          const float* __restrict__ Wv, const float* __restrict__ Wo,
                          const float* __restrict__ Wi, const float* __restrict__ Wo2,
                          __nv_bfloat16* __restrict__ WqkvH, __nv_bfloat16* __restrict__ WqkvL,
                          __nv_bfloat16* __restrict__ WoH,   __nv_bfloat16* __restrict__ WoL,
                          __nv_bfloat16* __restrict__ WiH,   __nv_bfloat16* __restrict__ WiL,
                          __nv_bfloat16* __restrict__ Wo2H,  __nv_bfloat16* __restrict__ Wo2L)
{
    const int l = blockIdx.y;
    const float* src; __nv_bfloat16 *dh, *dl;
    int R, Cc, outC, colOff;
    switch (blockIdx.z) {
        case 0: src = Wq;  dh = WqkvH; dl = WqkvL; R = HH; Cc = HH; outC = H3; colOff = 0;    break;
        case 1: src = Wk;  dh = WqkvH; dl = WqkvL; R = HH; Cc = HH; outC = H3; colOff = HH;   break;
        case 2: src = Wv;  dh = WqkvH; dl = WqkvL; R = HH; Cc = HH; outC = H3; colOff = 2*HH; break;
        case 3: src = Wo;  dh = WoH;   dl = WoL;   R = HH; Cc = HH; outC = HH; colOff = 0;    break;
        case 4: src = Wi;  dh = WiH;   dl = WiL;   R = HH; Cc = II; outC = II; colOff = 0;    break;
        default:src = Wo2; dh = Wo2H;  dl = Wo2L;  R = II; Cc = HH; outC = HH; colOff = 0;    break;
    }
    int id = blockIdx.x*256 + threadIdx.x;
    if (id >= R*Cc/4) return;
    int r = id / (Cc/4), c4 = id % (Cc/4);
    float4 v = *(const float4*)(src + (size_t)l*R*Cc + (size_t)r*Cc + c4*4);
    ushort4 hi, lo; split4(v, hi, lo);
    *(ushort4*)(dh + (size_t)l*R*outC + (size_t)r*outC + colOff + c4*4) = hi;
    *(ushort4*)(dl + (size_t)l*R*outC + (size_t)r*outC + colOff + c4*4) = lo;
}

__global__ void concat_bias(const float* __restrict__ bq, const float* __restrict__ bk,
                            const float* __restrict__ bv, float* __restrict__ dst)
{
    int id = blockIdx.x*256 + threadIdx.x;
    if (id >= LL*HH) return;
    int l = id / HH, c = id % HH;
    dst[(size_t)l*H3 + c]        = bq[id];
    dst[(size_t)l*H3 + HH + c]   = bk[id];
    dst[(size_t)l*H3 + 2*HH + c] = bv[id];
}

__global__ void split_x(const float* __restrict__ src,
                        __nv_bfloat16* __restrict__ dh,
                        __nv_bfloat16* __restrict__ dl, int n4)
{
    int id = blockIdx.x*256 + threadIdx.x;
    if (id >= n4) return;
    float4 v = *(const float4*)(src + (size_t)id*4);
    ushort4 hi, lo; split4(v, hi, lo);
    *(ushort4*)(dh + (size_t)id*4) = hi;
    *(ushort4*)(dl + (size_t)id*4) = lo;
}

// ---------------------------------------------------------------------------
// bf16x3 GEMM, all-bf16 operands via cp.async, 3-stage pipeline.
// 256 threads (8 warps), 2 CTAs/SM. Block tile 128 x BN (BN = 128 or 64).
// BN=128: warp tile 32x64 (4x2 grid). BN=64: warp tile 32x32.
// EPI: 0 = bias -> split out; 1 = bias + residual -> fp32; 2 = bias+GELU -> split
// ---------------------------------------------------------------------------
template<int EPI, int BN>
__global__ void __launch_bounds__(256, 2)
gemm_cp(const __nv_bfloat16* __restrict__ AH, const __nv_bfloat16* __restrict__ AL, int lda,
        const __nv_bfloat16* __restrict__ BH, const __nv_bfloat16* __restrict__ BL, int ldb,
        const float* __restrict__ bias,
        const __nv_bfloat16* __restrict__ RH, const __nv_bfloat16* __restrict__ RL, int ldr,
        float* __restrict__ Cf,
        __nv_bfloat16* __restrict__ CH, __nv_bfloat16* __restrict__ CL,
        int ldc, int K)
{
    constexpr int LAS = 40;                 // A row stride (shorts)
    constexpr int LBS = BN + 8;             // B row stride (shorts)
    constexpr int ASZ = 128*LAS;
    constexpr int BSZ = 32*LBS;
    constexpr int STG = 2*ASZ + 2*BSZ;
    constexpr int NP  = BN/32;              // 16-col n-blocks per warp
    constexpr int WTN = BN/2;               // warp n-tile

    extern __shared__ __align__(16) unsigned short sm[];
    const uint32_t smb = smem_u32(sm);

    const int tid = threadIdx.x, lane = tid & 31, wid = tid >> 5;
    const int wm = wid >> 1, wn = wid & 1;
    const int m0 = blockIdx.y * 128, n0 = blockIdx.x * BN;

    float acc[2][NP*2][4] = {};

    auto issue = [&](int st, int k0) {
        const uint32_t base = smb + st*STG*2;
        #pragma unroll
        for (int it = 0; it < 2; ++it) {
            int id = tid + it*256;
            int r = id >> 2, cc = id & 3;                       // A: 4 chunks/row
            uint32_t d = base + (uint32_t)(r*LAS + cc*8)*2;
            const size_t off = (size_t)(m0+r)*lda + k0 + cc*8;
            CP_ASYNC16(d,         AH + off);
            CP_ASYNC16(d + ASZ*2, AL + off);
        }
        constexpr int BCH = BN/8;                               // chunks per B row
        #pragma unroll
        for (int it = 0; it < 32*BCH/256; ++it) {
            int id = tid + it*256;
            int r = id / BCH, cc = id % BCH;
            uint32_t d = base + 2*ASZ*2 + (uint32_t)(r*LBS + cc*8)*2;
            const size_t off = (size_t)(k0+r)*ldb + n0 + cc*8;
            CP_ASYNC16(d,         BH + off);
            CP_ASYNC16(d + BSZ*2, BL + off);
        }
    };

    const int nk = K / 32;
    issue(0, 0);  CP_COMMIT();
    issue(1, 32); CP_COMMIT();

    for (int kt = 0; kt < nk; ++kt) {
        CP_WAIT1();
        __syncthreads();
        if (kt + 2 < nk) issue((kt+2) % 3, (kt+2)*32);
        CP_COMMIT();

        const unsigned short* Ah = sm + (kt%3)*STG;
        const unsigned short* Al = Ah + ASZ;
        const unsigned short* Bh = Al + ASZ;
        const unsigned short* Bl = Bh + BSZ;

        #pragma unroll
        for (int ks = 0; ks < 2; ++ks) {
            uint32_t ah[2][4], al[2][4];
            #pragma unroll
            for (int mt = 0; mt < 2; ++mt) {
                int r = wm*32 + mt*16 + (lane & 15);
                int c = ks*16 + ((lane >> 4) << 3);
                ldsm_x4(ah[mt], smem_u32(Ah + r*LAS + c));
                ldsm_x4(al[mt], smem_u32(Al + r*LAS + c));
            }
            #pragma unroll
            for (int np = 0; np < NP; ++np) {
                uint32_t bh[4], bl[4];
                int off = (ks*16 + (lane & 15))*LBS + wn*WTN + np*16 + ((lane >> 4) << 3);
                ldsm_x4t(bh, smem_u32(Bh + off));
                ldsm_x4t(bl, smem_u32(Bl + off));
                #pragma unroll
                for (int s = 0; s < 2; ++s) {
                    const int nt = np*2 + s;
                    #pragma unroll
                    for (int mt = 0; mt < 2; ++mt) {
                        mma16816(acc[mt][nt], ah[mt], bh + s*2);
                        mma16816(acc[mt][nt], al[mt], bh + s*2);
                        mma16816(acc[mt][nt], ah[mt], bl + s*2);
                    }
                }
            }
        }
    }

    // --- epilogue ---
    #pragma unroll
    for (int mt = 0; mt < 2; ++mt) {
        #pragma unroll
        for (int nt = 0; nt < NP*2; ++nt) {
            const int row = m0 + wm*32 + mt*16 + (lane >> 2);
            const int col = n0 + wn*WTN + nt*8 + (lane & 3)*2;
            #pragma unroll
            for (int h = 0; h < 2; ++h) {
                const int r2 = row + h*8;
                float v0 = acc[mt][nt][h*2+0];
                float v1 = acc[mt][nt][h*2+1];
                v0 += bias[col]; v1 += bias[col+1];
                if (EPI == 1) {
                    const size_t ri = (size_t)r2*ldr + col;
                    const ushort2 rh = *(const ushort2*)(RH + ri);
                    const ushort2 rl = *(const ushort2*)(RL + ri);
                    v0 += bf2f(rh.x) + bf2f(rl.x);
                    v1 += bf2f(rh.y) + bf2f(rl.y);
                    *(float2*)(Cf + (size_t)r2*ldc + col) = make_float2(v0, v1);
                } else {
                    if (EPI == 2) {
                        v0 = 0.5f*v0*(1.0f + erff(v0 * 0.70710678118654752f));
                        v1 = 0.5f*v1*(1.0f + erff(v1 * 0.70710678118654752f));
                    }
                    unsigned short h0, l0, h1, l1;
                    split1(v0, h0, l0); split1(v1, h1, l1);
                    const size_t ci = (size_t)r2*ldc + col;
                    *(ushort2*)(CH + ci) = make_ushort2(h0, h1);
                    *(ushort2*)(CL + ci) = make_ushort2(l0, l1);
                }
            }
        }
    }
}

#define GEMM_SMEM_128 (3 * (2*(128*40) + 2*(32*136)) * 2)   // 113664 B
#define GEMM_SMEM_64  (3 * (2*(128*40) + 2*(32*72))  * 2)   //  89088 B

// ---------------------------------------------------------------------------
// Fused flash attention; Q/K/V pre-split bf16 (ld = H3); ctx out as hi/lo.
// ---------------------------------------------------------------------------
#define FLASH_SMEM (6*128*(64+8)*2)   // 110592 B

__global__ void __launch_bounds__(256, 1)
flash_attn(const __nv_bfloat16* __restrict__ QKVH,
           const __nv_bfloat16* __restrict__ QKVL,
           __nv_bfloat16* __restrict__ OH, __nv_bfloat16* __restrict__ OL)
{
    constexpr int DP  = DHH + 8;
    constexpr int QSZ = 128*DP;

    extern __shared__ __align__(16) unsigned short dynsm[];
    unsigned short* Qh = dynsm;
    unsigned short* Ql = Qh + QSZ;
    unsigned short* Kh = Ql + QSZ;
    unsigned short* Kl = Kh + QSZ;
    unsigned short* Vh = Kl + QSZ;
    unsigned short* Vl = Vh + QSZ;

    const int tid = threadIdx.x, lane = tid & 31, w = tid >> 5;
    const int b = blockIdx.y / NHH, hh = blockIdx.y % NHH;
    const int q0 = blockIdx.x * 128;
    const size_t qoff = ((size_t)b*SS + q0)*H3 + hh*DHH;
    const size_t koff = (size_t)b*SS*H3 + HH + hh*DHH;
    const size_t voff = (size_t)b*SS*H3 + 2*HH + hh*DHH;

    #pragma unroll
    for (int it = 0; it < 4; ++it) {
        int id = tid + it*256;
        int r = id >> 3, c8 = id & 7;
        *(uint4*)&Qh[r*DP + c8*8] = *(const uint4*)(QKVH + qoff + (size_t)r*H3 + c8*8);
        *(uint4*)&Ql[r*DP + c8*8] = *(const uint4*)(QKVL + qoff + (size_t)r*H3 + c8*8);
    }
    __syncthreads();

    uint32_t qh[4][4], ql[4][4];
    {
        int r = w*16 + (lane & 15);
        #pragma unroll
        for (int ks = 0; ks < 4; ++ks) {
            int c = ks*16 + ((lane >> 4) << 3);
            ldsm_x4(qh[ks], smem_u32(Qh + r*DP + c));
            ldsm_x4(ql[ks], smem_u32(Ql + r*DP + c));
        }
    }

    float oacc[8][4] = {};
    float mrow[2] = {-1e30f, -1e30f};
    float lrow[2] = {0.0f, 0.0f};

    const int kb_row = (lane & 7) + ((lane & 16) >> 1);
    const int kb_col = ((lane >> 3) & 1) * 8;

    for (int j = 0; j < 4; ++j) {
        const size_t s0 = (size_t)j*128;
        #pragma unroll
        for (int it = 0; it < 4; ++it) {
            int id = tid + it*256;
            int r = id >> 3, c8 = id & 7;
            const size_t gk = koff + (s0+r)*H3 + c8*8;
            const size_t gv = voff + (s0+r)*H3 + c8*8;
            *(uint4*)&Kh[r*DP + c8*8] = *(const uint4*)(QKVH + gk);
            *(uint4*)&Kl[r*DP + c8*8] = *(const uint4*)(QKVL + gk);
            *(uint4*)&Vh[r*DP + c8*8] = *(const uint4*)(QKVH + gv);
            *(uint4*)&Vl[r*DP + c8*8] = *(const uint4*)(QKVL + gv);
        }
        __syncthreads();

        float sacc[16][4] = {};
        #pragma unroll
        for (int ks = 0; ks < 4; ++ks) {
            #pragma unroll
            for (int np = 0; np < 8; ++np) {
                uint32_t bh[4], bl[4];
                int off = (np*16 + kb_row)*DP + ks*16 + kb_col;
                ldsm_x4(bh, smem_u32(Kh + off));
                ldsm_x4(bl, smem_u32(Kl + off));
                #pragma unroll
                for (int s = 0; s < 2; ++s) {
                    int nt = np*2 + s;
                    mma16816(sacc[nt], qh[ks], bh + s*2);
                    mma16816(sacc[nt], ql[ks], bh + s*2);
                    mma16816(sacc[nt], qh[ks], bl + s*2);
                }
            }
        }
        #pragma unroll
        for (int nt = 0; nt < 16; ++nt) {
            sacc[nt][0] *= 0.125f; sacc[nt][1] *= 0.125f;
            sacc[nt][2] *= 0.125f; sacc[nt][3] *= 0.125f;
        }

        #pragma unroll
        for (int h = 0; h < 2; ++h) {
            float mx = -1e30f;
            #pragma unroll
            for (int nt = 0; nt < 16; ++nt)
                mx = fmaxf(mx, fmaxf(sacc[nt][2*h], sacc[nt][2*h+1]));
            mx = fmaxf(mx, __shfl_xor_sync(0xffffffffu, mx, 1));
            mx = fmaxf(mx, __shfl_xor_sync(0xffffffffu, mx, 2));
            float mnew = fmaxf(mrow[h], mx);
            float corr = expf(mrow[h] - mnew);
            mrow[h] = mnew;
            float sum = 0.0f;
            #pragma unroll
            for (int nt = 0; nt < 16; ++nt) {
                float p0 = expf(sacc[nt][2*h]   - mnew);
                float p1 = expf(sacc[nt][2*h+1] - mnew);
                sacc[nt][2*h] = p0; sacc[nt][2*h+1] = p1;
                sum += p0 + p1;
            }
            sum += __shfl_xor_sync(0xffffffffu, sum, 1);
            sum += __shfl_xor_sync(0xffffffffu, sum, 2);
            lrow[h] = lrow[h]*corr + sum;
            #pragma unroll
            for (int nt = 0; nt < 8; ++nt) {
                oacc[nt][2*h]   *= corr;
                oacc[nt][2*h+1] *= corr;
            }
        }

        #pragma unroll
        for (int ks = 0; ks < 8; ++ks) {
            uint32_t ph[4], pl[4];
            #pragma unroll
            for (int q = 0; q < 2; ++q) {
                #pragma unroll
                for (int hf = 0; hf < 2; ++hf) {
                    float x = sacc[2*ks+q][2*hf];
                    float y = sacc[2*ks+q][2*hf+1];
                    unsigned short hx, lx, hy, ly;
                    split1(x, hx, lx); split1(y, hy, ly);
                    ph[2*q+hf] = (uint32_t)hx | ((uint32_t)hy << 16);
                    pl[2*q+hf] = (uint32_t)lx | ((uint32_t)ly << 16);
                }
            }
            #pragma unroll
            for (int np = 0; np < 4; ++np) {
                uint32_t bh[4], bl[4];
                int off = (ks*16 + (lane & 15))*DP + np*16 + ((lane >> 4) << 3);
                ldsm_x4t(bh, smem_u32(Vh + off));
                ldsm_x4t(bl, smem_u32(Vl + off));
                #pragma unroll
                for (int s = 0; s < 2; ++s) {
                    int nt = np*2 + s;
                    mma16816(oacc[nt], ph, bh + s*2);
                    mma16816(oacc[nt], pl, bh + s*2);
                    mma16816(oacc[nt], ph, bl + s*2);
                }
            }
        }
        __syncthreads();
    }

    const size_t obase = (size_t)b*SS*HH + (size_t)hh*DHH;
    const int orow = w*16 + (lane >> 2);
    #pragma unroll
    for (int h = 0; h < 2; ++h) {
        const float inv = 1.0f / lrow[h];
        const int r = q0 + orow + h*8;
        #pragma unroll
        for (int nt = 0; nt < 8; ++nt) {
            const int c = nt*8 + (lane & 3)*2;
            unsigned short h0, l0, h1, l1;
            split1(oacc[nt][2*h]*inv,   h0, l0);
            split1(oacc[nt][2*h+1]*inv, h1, l1);
            const size_t oi = obase + (size_t)r*HH + c;
            *(ushort2*)(OH + oi) = make_ushort2(h0, h1);
            *(ushort2*)(OL + oi) = make_ushort2(l0, l1);
        }
    }
}

// ---------------------------------------------------------------------------
// LayerNorm (warp per row). SPLIT=1 -> bf16 hi/lo out; SPLIT=0 -> fp32 out.
// ---------------------------------------------------------------------------
template<int SPLIT>
__global__ void layernorm768(const float* __restrict__ X,
                             const float* __restrict__ g,
                             const float* __restrict__ b,
                             float* __restrict__ Yf,
                             __nv_bfloat16* __restrict__ YH,
                             __nv_bfloat16* __restrict__ YL, int rows)
{
    const int warp = (blockIdx.x * blockDim.x + threadIdx.x) >> 5;
    const int lane = threadIdx.x & 31;
    if (warp >= rows) return;
    const float4* x = (const float4*)(X + (size_t)warp * 768);

    float4 v[6];
    float s = 0.0f;
    #pragma unroll
    for (int i = 0; i < 6; ++i) {
        v[i] = x[lane + i*32];
        s += v[i].x + v[i].y + v[i].z + v[i].w;
    }
    #pragma unroll
    for (int o = 16; o; o >>= 1) s += __shfl_xor_sync(0xffffffffu, s, o);
    const float mean = s * (1.0f / 768.0f);

    float var = 0.0f;
    #pragma unroll
    for (int i = 0; i < 6; ++i) {
        float dx = v[i].x - mean, dy = v[i].y - mean, dz = v[i].z - mean, dw = v[i].w - mean;
        var += dx*dx + dy*dy + dz*dz + dw*dw;
    }
    #pragma unroll
    for (int o = 16; o; o >>= 1) var += __shfl_xor_sync(0xffffffffu, var, o);
    const float rs = rsqrtf(var * (1.0f / 768.0f) + 1e-12f);

    const float4* gg = (const float4*)g;
    const float4* bb = (const float4*)b;
    #pragma unroll
    for (int i = 0; i < 6; ++i) {
        const int c = lane + i*32;
        const float4 gv = gg[c], bv = bb[c];
        float4 o4;
        o4.x = (v[i].x - mean) * rs * gv.x + bv.x;
        o4.y = (v[i].y - mean) * rs * gv.y + bv.y;
        o4.z = (v[i].z - mean) * rs * gv.z + bv.z;
        o4.w = (v[i].w - mean) * rs * gv.w + bv.w;
        if (SPLIT) {
            ushort4 hi, lo; split4(o4, hi, lo);
            *(ushort4*)(YH + (size_t)warp*768 + c*4) = hi;
            *(ushort4*)(YL + (size_t)warp*768 + c*4) = lo;
        } else {
            *(float4*)(Yf + (size_t)warp*768 + c*4) = o4;
        }
    }
}

// ---------------------------------------------------------------------------
// Launch
// ---------------------------------------------------------------------------
extern "C" void kernel_launch(void* const* d_in, const int* in_sizes, int n_in,
                              void* d_out, int out_size)
{
    (void)in_sizes; (void)n_in; (void)out_size;
    const float* hs  = (const float*)d_in[0];
    const float* Wq  = (const float*)d_in[1];  const float* bq  = (const float*)d_in[2];
    const float* Wk  = (const float*)d_in[3];  const float* bk  = (const float*)d_in[4];
    const float* Wv  = (const float*)d_in[5];  const float* bv  = (const float*)d_in[6];
    const float* Wo  = (const float*)d_in[7];  const float* bo  = (const float*)d_in[8];
    const float* g1  = (const float*)d_in[9];  const float* b1  = (const float*)d_in[10];
    const float* Wi  = (const float*)d_in[11]; const float* bi  = (const float*)d_in[12];
    const float* Wo2 = (const float*)d_in[13]; const float* bo2 = (const float*)d_in[14];
    const float* g2  = (const float*)d_in[15]; const float* b2  = (const float*)d_in[16];

    __nv_bfloat16 *XH, *XL, *QKVH, *QKVL, *CH, *CL, *AH, *AL, *IH, *IL;
    __nv_bfloat16 *WqkvH, *WqkvL, *WoH, *WoL, *WiH, *WiL, *Wo2H, *Wo2L;
    float *T, *bqkv;
    cudaGetSymbolAddress((void**)&XH, g_XH);   cudaGetSymbolAddress((void**)&XL, g_XL);
    cudaGetSymbolAddress((void**)&QKVH, g_QKVH); cudaGetSymbolAddress((void**)&QKVL, g_QKVL);
    cudaGetSymbolAddress((void**)&CH, g_CH);   cudaGetSymbolAddress((void**)&CL, g_CL);
    cudaGetSymbolAddress((void**)&AH, g_AH);   cudaGetSymbolAddress((void**)&AL, g_AL);
    cudaGetSymbolAddress((void**)&IH, g_IH);   cudaGetSymbolAddress((void**)&IL, g_IL);
    cudaGetSymbolAddress((void**)&T,  g_T);    cudaGetSymbolAddress((void**)&bqkv, g_bqkv);
    cudaGetSymbolAddress((void**)&WqkvH, g_WqkvH); cudaGetSymbolAddress((void**)&WqkvL, g_WqkvL);
    cudaGetSymbolAddress((void**)&WoH, g_WoH); cudaGetSymbolAddress((void**)&WoL, g_WoL);
    cudaGetSymbolAddress((void**)&WiH, g_WiH); cudaGetSymbolAddress((void**)&WiL, g_WiL);
    cudaGetSymbolAddress((void**)&Wo2H, g_Wo2H); cudaGetSymbolAddress((void**)&Wo2L, g_Wo2L);

    cudaFuncSetAttribute(gemm_cp<0,128>, cudaFuncAttributeMaxDynamicSharedMemorySize, GEMM_SMEM_128);
    cudaFuncSetAttribute(gemm_cp<2,128>, cudaFuncAttributeMaxDynamicSharedMemorySize, GEMM_SMEM_128);
    cudaFuncSetAttribute(gemm_cp<1,64>,  cudaFuncAttributeMaxDynamicSharedMemorySize, GEMM_SMEM_64);
    cudaFuncSetAttribute(flash_attn, cudaFuncAttributeMaxDynamicSharedMemorySize, FLASH_SMEM);

    // --- preprocessing (3 launches so ncu -s 5 lands on a real GEMM) ---
    split_all<<<dim3(HH*II/1024, LL, 6), 256>>>(Wq, Wk, Wv, Wo, Wi, Wo2,
        WqkvH, WqkvL, WoH, WoL, WiH, WiL, Wo2H, Wo2L);
    concat_bias<<<(LL*HH + 255)/256, 256>>>(bq, bk, bv, bqkv);
    split_x<<<(M0*HH/4 + 255)/256, 256>>>(hs, XH, XL, M0*HH/4);

    for (int l = 0; l < LL; ++l) {
        const __nv_bfloat16* wqkvH = WqkvH + (size_t)l*HH*H3;
        const __nv_bfloat16* wqkvL = WqkvL + (size_t)l*HH*H3;
        const __nv_bfloat16* woH   = WoH   + (size_t)l*HH*HH;
        const __nv_bfloat16* woL   = WoL   + (size_t)l*HH*HH;
        const __nv_bfloat16* wiH   = WiH   + (size_t)l*HH*II;
        const __nv_bfloat16* wiL   = WiL   + (size_t)l*HH*II;
        const __nv_bfloat16* wo2H  = Wo2H  + (size_t)l*II*HH;
        const __nv_bfloat16* wo2L  = Wo2L  + (size_t)l*II*HH;
        const float* bqkvl = bqkv + (size_t)l*H3;
        const float* bol   = bo   + (size_t)l*HH;
        const float* bil   = bi   + (size_t)l*II;
        const float* bo2l  = bo2  + (size_t)l*HH;

        // QKV projection (N=2304, BN=128)
        gemm_cp<0,128><<<dim3(H3/128, M0/128), 256, GEMM_SMEM_128>>>(
            XH, XL, HH, wqkvH, wqkvL, H3, bqkvl,
            nullptr, nullptr, 0, nullptr, QKVH, QKVL, H3, HH);

        // fused attention -> ctx (hi/lo)
        flash_attn<<<dim3(SS/128, NBA), 256, FLASH_SMEM>>>(QKVH, QKVL, CH, CL);

        // O projection + residual(X) -> T (fp32)   (N=768, BN=64: 768 CTAs)
        gemm_cp<1,64><<<dim3(HH/64, M0/128), 256, GEMM_SMEM_64>>>(
            CH, CL, HH, woH, woL, HH, bol,
            XH, XL, HH, T, nullptr, nullptr, HH, HH);
        layernorm768<1><<<M0/8, 256>>>(T, g1 + (size_t)l*HH, b1 + (size_t)l*HH,
                                       nullptr, AH, AL, M0);

        // FFN1: I = gelu(A @ Wi + bi)   (N=3072, BN=128)
        gemm_cp<2,128><<<dim3(II/128, M0/128), 256, GEMM_SMEM_128>>>(
            AH, AL, HH, wiH, wiL, II, bil,
            nullptr, nullptr, 0, nullptr, IH, IL, II, HH);

        // FFN2 + residual(A) -> T (fp32)   (N=768, BN=64: 768 CTAs)
        gemm_cp<1,64><<<dim3(HH/64, M0/128), 256, GEMM_SMEM_64>>>(
            IH, IL, II, wo2H, wo2L, HH, bo2l,
            AH, AL, HH, T, nullptr, nullptr, HH, II);

        if (l == LL-1) {
            layernorm768<0><<<M0/8, 256>>>(T, g2 + (size_t)l*HH, b2 + (size_t)l*HH,
                                           (float*)d_out, nullptr, nullptr, M0);
        } else {
            layernorm768<1><<<M0/8, 256>>>(T, g2 + (size_t)l*HH, b2 + (size_t)l*HH,
                                           nullptr, XH, XL, M0);
        }
    }
}

// round 12
// speedup vs baseline: 1.0256x; 1.0256x over previous
#include <cuda_runtime.h>
#include <cuda_bf16.h>
#include <math.h>
#include <stdint.h>

// Problem constants
#define BB   16
#define SS   512
#define HH   768
#define II   3072
#define NHH  12
#define DHH  64
#define LL   6
#define M0   (BB*SS)       // 8192 tokens
#define NBA  (BB*NHH)      // 192 attention batches
#define H3   (3*HH)        // 2304

// ---------------------------------------------------------------------------
// Scratch buffers (activations as bf16 hi/lo pairs; T fp32 for LayerNorm)
// ---------------------------------------------------------------------------
__device__ __nv_bfloat16 g_XH[M0*HH],   g_XL[M0*HH];
__device__ __nv_bfloat16 g_QKVH[M0*H3], g_QKVL[M0*H3];
__device__ __nv_bfloat16 g_CH[M0*HH],   g_CL[M0*HH];
__device__ __nv_bfloat16 g_AH[M0*HH],   g_AL[M0*HH];
__device__ __nv_bfloat16 g_IH[M0*II],   g_IL[M0*II];
__device__ float g_T[M0*HH];
// pre-split bf16 weights (hi/lo), original [K][N] layout
__device__ __nv_bfloat16 g_WqkvH[LL*HH*H3], g_WqkvL[LL*HH*H3];
__device__ __nv_bfloat16 g_WoH[LL*HH*HH],   g_WoL[LL*HH*HH];
__device__ __nv_bfloat16 g_WiH[LL*HH*II],   g_WiL[LL*HH*II];
__device__ __nv_bfloat16 g_Wo2H[LL*II*HH],  g_Wo2L[LL*II*HH];
__device__ float g_bqkv[LL*H3];

// ---------------------------------------------------------------------------
// PTX helpers
// ---------------------------------------------------------------------------
__device__ __forceinline__ uint32_t smem_u32(const void* p) {
    return (uint32_t)__cvta_generic_to_shared(p);
}
__device__ __forceinline__ void ldsm_x4(uint32_t* r, uint32_t a) {
    asm volatile("ldmatrix.sync.aligned.m8n8.x4.shared.b16 {%0,%1,%2,%3}, [%4];"
        : "=r"(r[0]), "=r"(r[1]), "=r"(r[2]), "=r"(r[3]) : "r"(a));
}
__device__ __forceinline__ void ldsm_x4t(uint32_t* r, uint32_t a) {
    asm volatile("ldmatrix.sync.aligned.m8n8.x4.trans.shared.b16 {%0,%1,%2,%3}, [%4];"
        : "=r"(r[0]), "=r"(r[1]), "=r"(r[2]), "=r"(r[3]) : "r"(a));
}
__device__ __forceinline__ void mma16816(float* c, const uint32_t* a, const uint32_t* b) {
    asm volatile(
        "mma.sync.aligned.m16n8k16.row.col.f32.bf16.bf16.f32 "
        "{%0,%1,%2,%3}, {%4,%5,%6,%7}, {%8,%9}, {%0,%1,%2,%3};"
        : "+f"(c[0]), "+f"(c[1]), "+f"(c[2]), "+f"(c[3])
        : "r"(a[0]), "r"(a[1]), "r"(a[2]), "r"(a[3]), "r"(b[0]), "r"(b[1]));
}
#define CP_ASYNC16(dst, src) \
    asm volatile("cp.async.cg.shared.global [%0], [%1], 16;" :: "r"(dst), "l"(src) : "memory")
#define CP_COMMIT() asm volatile("cp.async.commit_group;" ::: "memory")
#define CP_WAIT1()  asm volatile("cp.async.wait_group 1;" ::: "memory")

// fp32 -> (bf16 hi, bf16 lo) exact-residual split
__device__ __forceinline__ void split1(float x, unsigned short& hi, unsigned short& lo) {
    __nv_bfloat16 h = __float2bfloat16(x);
    hi = *reinterpret_cast<unsigned short*>(&h);
    float r = x - __bfloat162float(h);
    __nv_bfloat16 l = __float2bfloat16(r);
    lo = *reinterpret_cast<unsigned short*>(&l);
}
__device__ __forceinline__ void split4(float4 v, ushort4& hi, ushort4& lo) {
    split1(v.x, hi.x, lo.x);
    split1(v.y, hi.y, lo.y);
    split1(v.z, hi.z, lo.z);
    split1(v.w, hi.w, lo.w);
}
__device__ __forceinline__ float bf2f(unsigned short u) {
    __nv_bfloat16 h = *reinterpret_cast<__nv_bfloat16*>(&u);
    return __bfloat162float(h);
}

// ---------------------------------------------------------------------------
// Preprocessing: ALL weight splits in ONE launch (blockIdx.z selects matrix)
// ---------------------------------------------------------------------------
__global__ void split_all(const float* __restrict__ Wq, const float* __restrict__ Wk,
                          const float* __restrict__ Wv, const float* __restrict__ Wo,
                          const float* __restrict__ Wi, const float* __restrict__ Wo2,
                          __nv_bfloat16* __restrict__ WqkvH, __nv_bfloat16* __restrict__ WqkvL,
                          __nv_bfloat16* __restrict__ WoH,   __nv_bfloat16* __restrict__ WoL,
                          __nv_bfloat16* __restrict__ WiH,   __nv_bfloat16* __restrict__ WiL,
                          __nv_bfloat16* __restrict__ Wo2H,  __nv_bfloat16* __restrict__ Wo2L)
{
    const int l = blockIdx.y;
    const float* src; __nv_bfloat16 *dh, *dl;
    int R, Cc, outC, colOff;
    switch (blockIdx.z) {
        case 0: src = Wq;  dh = WqkvH; dl = WqkvL; R = HH; Cc = HH; outC = H3; colOff = 0;    break;
        case 1: src = Wk;  dh = WqkvH; dl = WqkvL; R = HH; Cc = HH; outC = H3; colOff = HH;   break;
        case 2: src = Wv;  dh = WqkvH; dl = WqkvL; R = HH; Cc = HH; outC = H3; colOff = 2*HH; break;
        case 3: src = Wo;  dh = WoH;   dl = WoL;   R = HH; Cc = HH; outC = HH; colOff = 0;    break;
        case 4: src = Wi;  dh = WiH;   dl = WiL;   R = HH; Cc = II; outC = II; colOff = 0;    break;
        default:src = Wo2; dh = Wo2H;  dl = Wo2L;  R = II; Cc = HH; outC = HH; colOff = 0;    break;
    }
    int id = blockIdx.x*256 + threadIdx.x;
    if (id >= R*Cc/4) return;
    int r = id / (Cc/4), c4 = id % (Cc/4);
    float4 v = *(const float4*)(src + (size_t)l*R*Cc + (size_t)r*Cc + c4*4);
    ushort4 hi, lo; split4(v, hi, lo);
    *(ushort4*)(dh + (size_t)l*R*outC + (size_t)r*outC + colOff + c4*4) = hi;
    *(ushort4*)(dl + (size_t)l*R*outC + (size_t)r*outC + colOff + c4*4) = lo;
}

__global__ void concat_bias(const float* __restrict__ bq, const float* __restrict__ bk,
                            const float* __restrict__ bv, float* __restrict__ dst)
{
    int id = blockIdx.x*256 + threadIdx.x;
    if (id >= LL*HH) return;
    int l = id / HH, c = id % HH;
    dst[(size_t)l*H3 + c]        = bq[id];
    dst[(size_t)l*H3 + HH + c]   = bk[id];
    dst[(size_t)l*H3 + 2*HH + c] = bv[id];
}

__global__ void split_x(const float* __restrict__ src,
                        __nv_bfloat16* __restrict__ dh,
                        __nv_bfloat16* __restrict__ dl, int n4)
{
    int id = blockIdx.x*256 + threadIdx.x;
    if (id >= n4) return;
    float4 v = *(const float4*)(src + (size_t)id*4);
    ushort4 hi, lo; split4(v, hi, lo);
    *(ushort4*)(dh + (size_t)id*4) = hi;
    *(ushort4*)(dl + (size_t)id*4) = lo;
}

// ---------------------------------------------------------------------------
// bf16x3 GEMM, all-bf16 operands via cp.async, 3-stage pipeline.
// 256 threads (8 warps, warp tile 32x64), 2 CTAs/SM. Block tile 128x128x32.
// Split MMAs issued TERM-OUTER: same-accumulator MMAs are >=4 issues apart
// (breaks the hh->lh->hl RAW chain that held tensor pipe at 59%).
// EPI: 0 = bias -> split out; 1 = bias + residual -> fp32; 2 = bias+GELU -> split
// ---------------------------------------------------------------------------
#define LAS   40            // A row stride (shorts): 32 + 8 pad
#define LBS   136           // B row stride (shorts): 128 + 8 pad
#define ASZ   (128*LAS)
#define BSZ   (32*LBS)
#define STG   (2*ASZ + 2*BSZ)
#define GEMM_SMEM (3*STG*2)            // 113664 B

template<int EPI>
__global__ void __launch_bounds__(256, 2)
gemm_cp(const __nv_bfloat16* __restrict__ AH, const __nv_bfloat16* __restrict__ AL, int lda,
        const __nv_bfloat16* __restrict__ BH, const __nv_bfloat16* __restrict__ BL, int ldb,
        const float* __restrict__ bias,
        const __nv_bfloat16* __restrict__ RH, const __nv_bfloat16* __restrict__ RL, int ldr,
        float* __restrict__ Cf,
        __nv_bfloat16* __restrict__ CH, __nv_bfloat16* __restrict__ CL,
        int ldc, int K)
{
    extern __shared__ __align__(16) unsigned short sm[];
    const uint32_t smb = smem_u32(sm);

    const int tid = threadIdx.x, lane = tid & 31, wid = tid >> 5;
    const int wm = wid >> 1, wn = wid & 1;          // 4x2 warp grid, tile 32x64
    const int m0 = blockIdx.y * 128, n0 = blockIdx.x * 128;

    float acc[2][8][4] = {};

    auto issue = [&](int st, int k0) {
        const uint32_t base = smb + st*STG*2;
        #pragma unroll
        for (int it = 0; it < 2; ++it) {
            int id = tid + it*256;
            int r = id >> 2, cc = id & 3;                       // A: 4 chunks/row
            uint32_t d = base + (uint32_t)(r*LAS + cc*8)*2;
            const size_t off = (size_t)(m0+r)*lda + k0 + cc*8;
            CP_ASYNC16(d,         AH + off);
            CP_ASYNC16(d + ASZ*2, AL + off);
        }
        #pragma unroll
        for (int it = 0; it < 2; ++it) {
            int id = tid + it*256;
            int r = id >> 4, cc = id & 15;                      // B: 16 chunks/row
            uint32_t d = base + 2*ASZ*2 + (uint32_t)(r*LBS + cc*8)*2;
            const size_t off = (size_t)(k0+r)*ldb + n0 + cc*8;
            CP_ASYNC16(d,         BH + off);
            CP_ASYNC16(d + BSZ*2, BL + off);
        }
    };

    const int nk = K / 32;
    issue(0, 0);  CP_COMMIT();
    issue(1, 32); CP_COMMIT();

    for (int kt = 0; kt < nk; ++kt) {
        CP_WAIT1();
        __syncthreads();
        if (kt + 2 < nk) issue((kt+2) % 3, (kt+2)*32);
        CP_COMMIT();

        const unsigned short* Ah = sm + (kt%3)*STG;
        const unsigned short* Al = Ah + ASZ;
        const unsigned short* Bh = Al + ASZ;
        const unsigned short* Bl = Bh + BSZ;

        #pragma unroll
        for (int ks = 0; ks < 2; ++ks) {
            uint32_t ah[2][4], al[2][4];
            #pragma unroll
            for (int mt = 0; mt < 2; ++mt) {
                int r = wm*32 + mt*16 + (lane & 15);
                int c = ks*16 + ((lane >> 4) << 3);
                ldsm_x4(ah[mt], smem_u32(Ah + r*LAS + c));
                ldsm_x4(al[mt], smem_u32(Al + r*LAS + c));
            }
            #pragma unroll
            for (int np = 0; np < 4; ++np) {
                uint32_t bh[4], bl[4];
                int off = (ks*16 + (lane & 15))*LBS + wn*64 + np*16 + ((lane >> 4) << 3);
                ldsm_x4t(bh, smem_u32(Bh + off));
                ldsm_x4t(bl, smem_u32(Bl + off));
                // term-outer: same-acc MMAs 4 issues apart (no RAW chain)
                #pragma unroll
                for (int s = 0; s < 2; ++s)
                    #pragma unroll
                    for (int mt = 0; mt < 2; ++mt)
                        mma16816(acc[mt][np*2+s], ah[mt], bh + s*2);
                #pragma unroll
                for (int s = 0; s < 2; ++s)
                    #pragma unroll
                    for (int mt = 0; mt < 2; ++mt)
                        mma16816(acc[mt][np*2+s], al[mt], bh + s*2);
                #pragma unroll
                for (int s = 0; s < 2; ++s)
                    #pragma unroll
                    for (int mt = 0; mt < 2; ++mt)
                        mma16816(acc[mt][np*2+s], ah[mt], bl + s*2);
            }
        }
    }

    // --- epilogue ---
    #pragma unroll
    for (int mt = 0; mt < 2; ++mt) {
        #pragma unroll
        for (int nt = 0; nt < 8; ++nt) {
            const int row = m0 + wm*32 + mt*16 + (lane >> 2);
            const int col = n0 + wn*64 + nt*8 + (lane & 3)*2;
            #pragma unroll
            for (int h = 0; h < 2; ++h) {
                const int r2 = row + h*8;
                float v0 = acc[mt][nt][h*2+0];
                float v1 = acc[mt][nt][h*2+1];
                v0 += bias[col]; v1 += bias[col+1];
                if (EPI == 1) {
                    const size_t ri = (size_t)r2*ldr + col;
                    const ushort2 rh = *(const ushort2*)(RH + ri);
                    const ushort2 rl = *(const ushort2*)(RL + ri);
                    v0 += bf2f(rh.x) + bf2f(rl.x);
                    v1 += bf2f(rh.y) + bf2f(rl.y);
                    *(float2*)(Cf + (size_t)r2*ldc + col) = make_float2(v0, v1);
                } else {
                    if (EPI == 2) {
                        v0 = 0.5f*v0*(1.0f + erff(v0 * 0.70710678118654752f));
                        v1 = 0.5f*v1*(1.0f + erff(v1 * 0.70710678118654752f));
                    }
                    unsigned short h0, l0, h1, l1;
                    split1(v0, h0, l0); split1(v1, h1, l1);
                    const size_t ci = (size_t)r2*ldc + col;
                    *(ushort2*)(CH + ci) = make_ushort2(h0, h1);
                    *(ushort2*)(CL + ci) = make_ushort2(l0, l1);
                }
            }
        }
    }
}

// ---------------------------------------------------------------------------
// Fused flash attention; Q/K/V pre-split bf16 (ld = H3); ctx out as hi/lo.
// MMA term-reorder applied to QK^T and PV loops.
// ---------------------------------------------------------------------------
#define FLASH_SMEM (6*128*(64+8)*2)   // 110592 B

__global__ void __launch_bounds__(256, 1)
flash_attn(const __nv_bfloat16* __restrict__ QKVH,
           const __nv_bfloat16* __restrict__ QKVL,
           __nv_bfloat16* __restrict__ OH, __nv_bfloat16* __restrict__ OL)
{
    constexpr int DP  = DHH + 8;
    constexpr int QSZ = 128*DP;

    extern __shared__ __align__(16) unsigned short dynsm[];
    unsigned short* Qh = dynsm;
    unsigned short* Ql = Qh + QSZ;
    unsigned short* Kh = Ql + QSZ;
    unsigned short* Kl = Kh + QSZ;
    unsigned short* Vh = Kl + QSZ;
    unsigned short* Vl = Vh + QSZ;

    const int tid = threadIdx.x, lane = tid & 31, w = tid >> 5;
    const int b = blockIdx.y / NHH, hh = blockIdx.y % NHH;
    const int q0 = blockIdx.x * 128;
    const size_t qoff = ((size_t)b*SS + q0)*H3 + hh*DHH;
    const size_t koff = (size_t)b*SS*H3 + HH + hh*DHH;
    const size_t voff = (size_t)b*SS*H3 + 2*HH + hh*DHH;

    #pragma unroll
    for (int it = 0; it < 4; ++it) {
        int id = tid + it*256;
        int r = id >> 3, c8 = id & 7;
        *(uint4*)&Qh[r*DP + c8*8] = *(const uint4*)(QKVH + qoff + (size_t)r*H3 + c8*8);
        *(uint4*)&Ql[r*DP + c8*8] = *(const uint4*)(QKVL + qoff + (size_t)r*H3 + c8*8);
    }
    __syncthreads();

    uint32_t qh[4][4], ql[4][4];
    {
        int r = w*16 + (lane & 15);
        #pragma unroll
        for (int ks = 0; ks < 4; ++ks) {
            int c = ks*16 + ((lane >> 4) << 3);
            ldsm_x4(qh[ks], smem_u32(Qh + r*DP + c));
            ldsm_x4(ql[ks], smem_u32(Ql + r*DP + c));
        }
    }

    float oacc[8][4] = {};
    float mrow[2] = {-1e30f, -1e30f};
    float lrow[2] = {0.0f, 0.0f};

    const int kb_row = (lane & 7) + ((lane & 16) >> 1);
    const int kb_col = ((lane >> 3) & 1) * 8;

    for (int j = 0; j < 4; ++j) {
        const size_t s0 = (size_t)j*128;
        #pragma unroll
        for (int it = 0; it < 4; ++it) {
            int id = tid + it*256;
            int r = id >> 3, c8 = id & 7;
            const size_t gk = koff + (s0+r)*H3 + c8*8;
            const size_t gv = voff + (s0+r)*H3 + c8*8;
            *(uint4*)&Kh[r*DP + c8*8] = *(const uint4*)(QKVH + gk);
            *(uint4*)&Kl[r*DP + c8*8] = *(const uint4*)(QKVL + gk);
            *(uint4*)&Vh[r*DP + c8*8] = *(const uint4*)(QKVH + gv);
            *(uint4*)&Vl[r*DP + c8*8] = *(const uint4*)(QKVL + gv);
        }
        __syncthreads();

        float sacc[16][4] = {};
        #pragma unroll
        for (int ks = 0; ks < 4; ++ks) {
            #pragma unroll
            for (int np = 0; np < 8; ++np) {
                uint32_t bh[4], bl[4];
                int off = (np*16 + kb_row)*DP + ks*16 + kb_col;
                ldsm_x4(bh, smem_u32(Kh + off));
                ldsm_x4(bl, smem_u32(Kl + off));
                // term-outer reorder
                #pragma unroll
                for (int s = 0; s < 2; ++s) mma16816(sacc[np*2+s], qh[ks], bh + s*2);
                #pragma unroll
                for (int s = 0; s < 2; ++s) mma16816(sacc[np*2+s], ql[ks], bh + s*2);
                #pragma unroll
                for (int s = 0; s < 2; ++s) mma16816(sacc[np*2+s], qh[ks], bl + s*2);
            }
        }
        #pragma unroll
        for (int nt = 0; nt < 16; ++nt) {
            sacc[nt][0] *= 0.125f; sacc[nt][1] *= 0.125f;
            sacc[nt][2] *= 0.125f; sacc[nt][3] *= 0.125f;
        }

        #pragma unroll
        for (int h = 0; h < 2; ++h) {
            float mx = -1e30f;
            #pragma unroll
            for (int nt = 0; nt < 16; ++nt)
                mx = fmaxf(mx, fmaxf(sacc[nt][2*h], sacc[nt][2*h+1]));
            mx = fmaxf(mx, __shfl_xor_sync(0xffffffffu, mx, 1));
            mx = fmaxf(mx, __shfl_xor_sync(0xffffffffu, mx, 2));
            float mnew = fmaxf(mrow[h], mx);
            float corr = expf(mrow[h] - mnew);
            mrow[h] = mnew;
            float sum = 0.0f;
            #pragma unroll
            for (int nt = 0; nt < 16; ++nt) {
                float p0 = expf(sacc[nt][2*h]   - mnew);
                float p1 = expf(sacc[nt][2*h+1] - mnew);
                sacc[nt][2*h] = p0; sacc[nt][2*h+1] = p1;
                sum += p0 + p1;
            }
            sum += __shfl_xor_sync(0xffffffffu, sum, 1);
            sum += __shfl_xor_sync(0xffffffffu, sum, 2);
            lrow[h] = lrow[h]*corr + sum;
            #pragma unroll
            for (int nt = 0; nt < 8; ++nt) {
                oacc[nt][2*h]   *= corr;
                oacc[nt][2*h+1] *= corr;
            }
        }

        #pragma unroll
        for (int ks = 0; ks < 8; ++ks) {
            uint32_t ph[4], pl[4];
            #pragma unroll
            for (int q = 0; q < 2; ++q) {
                #pragma unroll
                for (int hf = 0; hf < 2; ++hf) {
                    float x = sacc[2*ks+q][2*hf];
                    float y = sacc[2*ks+q][2*hf+1];
                    unsigned short hx, lx, hy, ly;
                    split1(x, hx, lx); split1(y, hy, ly);
                    ph[2*q+hf] = (uint32_t)hx | ((uint32_t)hy << 16);
                    pl[2*q+hf] = (uint32_t)lx | ((uint32_t)ly << 16);
                }
            }
            #pragma unroll
            for (int np = 0; np < 4; ++np) {
                uint32_t bh[4], bl[4];
                int off = (ks*16 + (lane & 15))*DP + np*16 + ((lane >> 4) << 3);
                ldsm_x4t(bh, smem_u32(Vh + off));
                ldsm_x4t(bl, smem_u32(Vl + off));
                // term-outer reorder
                #pragma unroll
                for (int s = 0; s < 2; ++s) mma16816(oacc[np*2+s], ph, bh + s*2);
                #pragma unroll
                for (int s = 0; s < 2; ++s) mma16816(oacc[np*2+s], pl, bh + s*2);
                #pragma unroll
                for (int s = 0; s < 2; ++s) mma16816(oacc[np*2+s], ph, bl + s*2);
            }
        }
        __syncthreads();
    }

    const size_t obase = (size_t)b*SS*HH + (size_t)hh*DHH;
    const int orow = w*16 + (lane >> 2);
    #pragma unroll
    for (int h = 0; h < 2; ++h) {
        const float inv = 1.0f / lrow[h];
        const int r = q0 + orow + h*8;
        #pragma unroll
        for (int nt = 0; nt < 8; ++nt) {
            const int c = nt*8 + (lane & 3)*2;
            unsigned short h0, l0, h1, l1;
            split1(oacc[nt][2*h]*inv,   h0, l0);
            split1(oacc[nt][2*h+1]*inv, h1, l1);
            const size_t oi = obase + (size_t)r*HH + c;
            *(ushort2*)(OH + oi) = make_ushort2(h0, h1);
            *(ushort2*)(OL + oi) = make_ushort2(l0, l1);
        }
    }
}

// ---------------------------------------------------------------------------
// LayerNorm (warp per row). SPLIT=1 -> bf16 hi/lo out; SPLIT=0 -> fp32 out.
// ---------------------------------------------------------------------------
template<int SPLIT>
__global__ void layernorm768(const float* __restrict__ X,
                             const float* __restrict__ g,
                             const float* __restrict__ b,
                             float* __restrict__ Yf,
                             __nv_bfloat16* __restrict__ YH,
                             __nv_bfloat16* __restrict__ YL, int rows)
{
    const int warp = (blockIdx.x * blockDim.x + threadIdx.x) >> 5;
    const int lane = threadIdx.x & 31;
    if (warp >= rows) return;
    const float4* x = (const float4*)(X + (size_t)warp * 768);

    float4 v[6];
    float s = 0.0f;
    #pragma unroll
    for (int i = 0; i < 6; ++i) {
        v[i] = x[lane + i*32];
        s += v[i].x + v[i].y + v[i].z + v[i].w;
    }
    #pragma unroll
    for (int o = 16; o; o >>= 1) s += __shfl_xor_sync(0xffffffffu, s, o);
    const float mean = s * (1.0f / 768.0f);

    float var = 0.0f;
    #pragma unroll
    for (int i = 0; i < 6; ++i) {
        float dx = v[i].x - mean, dy = v[i].y - mean, dz = v[i].z - mean, dw = v[i].w - mean;
        var += dx*dx + dy*dy + dz*dz + dw*dw;
    }
    #pragma unroll
    for (int o = 16; o; o >>= 1) var += __shfl_xor_sync(0xffffffffu, var, o);
    const float rs = rsqrtf(var * (1.0f / 768.0f) + 1e-12f);

    const float4* gg = (const float4*)g;
    const float4* bb = (const float4*)b;
    #pragma unroll
    for (int i = 0; i < 6; ++i) {
        const int c = lane + i*32;
        const float4 gv = gg[c], bv = bb[c];
        float4 o4;
        o4.x = (v[i].x - mean) * rs * gv.x + bv.x;
        o4.y = (v[i].y - mean) * rs * gv.y + bv.y;
        o4.z = (v[i].z - mean) * rs * gv.z + bv.z;
        o4.w = (v[i].w - mean) * rs * gv.w + bv.w;
        if (SPLIT) {
            ushort4 hi, lo; split4(o4, hi, lo);
            *(ushort4*)(YH + (size_t)warp*768 + c*4) = hi;
            *(ushort4*)(YL + (size_t)warp*768 + c*4) = lo;
        } else {
            *(float4*)(Yf + (size_t)warp*768 + c*4) = o4;
        }
    }
}

// ---------------------------------------------------------------------------
// Launch
// ---------------------------------------------------------------------------
extern "C" void kernel_launch(void* const* d_in, const int* in_sizes, int n_in,
                              void* d_out, int out_size)
{
    (void)in_sizes; (void)n_in; (void)out_size;
    const float* hs  = (const float*)d_in[0];
    const float* Wq  = (const float*)d_in[1];  const float* bq  = (const float*)d_in[2];
    const float* Wk  = (const float*)d_in[3];  const float* bk  = (const float*)d_in[4];
    const float* Wv  = (const float*)d_in[5];  const float* bv  = (const float*)d_in[6];
    const float* Wo  = (const float*)d_in[7];  const float* bo  = (const float*)d_in[8];
    const float* g1  = (const float*)d_in[9];  const float* b1  = (const float*)d_in[10];
    const float* Wi  = (const float*)d_in[11]; const float* bi  = (const float*)d_in[12];
    const float* Wo2 = (const float*)d_in[13]; const float* bo2 = (const float*)d_in[14];
    const float* g2  = (const float*)d_in[15]; const float* b2  = (const float*)d_in[16];

    __nv_bfloat16 *XH, *XL, *QKVH, *QKVL, *CH, *CL, *AH, *AL, *IH, *IL;
    __nv_bfloat16 *WqkvH, *WqkvL, *WoH, *WoL, *WiH, *WiL, *Wo2H, *Wo2L;
    float *T, *bqkv;
    cudaGetSymbolAddress((void**)&XH, g_XH);   cudaGetSymbolAddress((void**)&XL, g_XL);
    cudaGetSymbolAddress((void**)&QKVH, g_QKVH); cudaGetSymbolAddress((void**)&QKVL, g_QKVL);
    cudaGetSymbolAddress((void**)&CH, g_CH);   cudaGetSymbolAddress((void**)&CL, g_CL);
    cudaGetSymbolAddress((void**)&AH, g_AH);   cudaGetSymbolAddress((void**)&AL, g_AL);
    cudaGetSymbolAddress((void**)&IH, g_IH);   cudaGetSymbolAddress((void**)&IL, g_IL);
    cudaGetSymbolAddress((void**)&T,  g_T);    cudaGetSymbolAddress((void**)&bqkv, g_bqkv);
    cudaGetSymbolAddress((void**)&WqkvH, g_WqkvH); cudaGetSymbolAddress((void**)&WqkvL, g_WqkvL);
    cudaGetSymbolAddress((void**)&WoH, g_WoH); cudaGetSymbolAddress((void**)&WoL, g_WoL);
    cudaGetSymbolAddress((void**)&WiH, g_WiH); cudaGetSymbolAddress((void**)&WiL, g_WiL);
    cudaGetSymbolAddress((void**)&Wo2H, g_Wo2H); cudaGetSymbolAddress((void**)&Wo2L, g_Wo2L);

    cudaFuncSetAttribute(gemm_cp<0>, cudaFuncAttributeMaxDynamicSharedMemorySize, GEMM_SMEM);
    cudaFuncSetAttribute(gemm_cp<1>, cudaFuncAttributeMaxDynamicSharedMemorySize, GEMM_SMEM);
    cudaFuncSetAttribute(gemm_cp<2>, cudaFuncAttributeMaxDynamicSharedMemorySize, GEMM_SMEM);
    cudaFuncSetAttribute(flash_attn, cudaFuncAttributeMaxDynamicSharedMemorySize, FLASH_SMEM);

    // --- preprocessing ---
    split_all<<<dim3(HH*II/1024, LL, 6), 256>>>(Wq, Wk, Wv, Wo, Wi, Wo2,
        WqkvH, WqkvL, WoH, WoL, WiH, WiL, Wo2H, Wo2L);
    concat_bias<<<(LL*HH + 255)/256, 256>>>(bq, bk, bv, bqkv);
    split_x<<<(M0*HH/4 + 255)/256, 256>>>(hs, XH, XL, M0*HH/4);

    for (int l = 0; l < LL; ++l) {
        const __nv_bfloat16* wqkvH = WqkvH + (size_t)l*HH*H3;
        const __nv_bfloat16* wqkvL = WqkvL + (size_t)l*HH*H3;
        const __nv_bfloat16* woH   = WoH   + (size_t)l*HH*HH;
        const __nv_bfloat16* woL   = WoL   + (size_t)l*HH*HH;
        const __nv_bfloat16* wiH   = WiH   + (size_t)l*HH*II;
        const __nv_bfloat16* wiL   = WiL   + (size_t)l*HH*II;
        const __nv_bfloat16* wo2H  = Wo2H  + (size_t)l*II*HH;
        const __nv_bfloat16* wo2L  = Wo2L  + (size_t)l*II*HH;
        const float* bqkvl = bqkv + (size_t)l*H3;
        const float* bol   = bo   + (size_t)l*HH;
        const float* bil   = bi   + (size_t)l*II;
        const float* bo2l  = bo2  + (size_t)l*HH;

        // QKV projection (N=2304)
        gemm_cp<0><<<dim3(H3/128, M0/128), 256, GEMM_SMEM>>>(
            XH, XL, HH, wqkvH, wqkvL, H3, bqkvl,
            nullptr, nullptr, 0, nullptr, QKVH, QKVL, H3, HH);

        // fused attention -> ctx (hi/lo)
        flash_attn<<<dim3(SS/128, NBA), 256, FLASH_SMEM>>>(QKVH, QKVL, CH, CL);

        // O projection + residual(X) -> T (fp32)
        gemm_cp<1><<<dim3(HH/128, M0/128), 256, GEMM_SMEM>>>(
            CH, CL, HH, woH, woL, HH, bol,
            XH, XL, HH, T, nullptr, nullptr, HH, HH);
        layernorm768<1><<<M0/8, 256>>>(T, g1 + (size_t)l*HH, b1 + (size_t)l*HH,
                                       nullptr, AH, AL, M0);

        // FFN1: I = gelu(A @ Wi + bi)
        gemm_cp<2><<<dim3(II/128, M0/128), 256, GEMM_SMEM>>>(
            AH, AL, HH, wiH, wiL, II, bil,
            nullptr, nullptr, 0, nullptr, IH, IL, II, HH);

        // FFN2 + residual(A) -> T (fp32)
        gemm_cp<1><<<dim3(HH/128, M0/128), 256, GEMM_SMEM>>>(
            IH, IL, II, wo2H, wo2L, HH, bo2l,
            AH, AL, HH, T, nullptr, nullptr, HH, II);

        if (l == LL-1) {
            layernorm768<0><<<M0/8, 256>>>(T, g2 + (size_t)l*HH, b2 + (size_t)l*HH,
                                           (float*)d_out, nullptr, nullptr, M0);
        } else {
            layernorm768<1><<<M0/8, 256>>>(T, g2 + (size_t)l*HH, b2 + (size_t)l*HH,
                                           nullptr, XH, XL, M0);
        }
    }
}

// round 13
// speedup vs baseline: 1.0389x; 1.0130x over previous
#include <cuda_runtime.h>
#include <cuda_bf16.h>
#include <math.h>
#include <stdint.h>

// Problem constants
#define BB   16
#define SS   512
#define HH   768
#define II   3072
#define NHH  12
#define DHH  64
#define LL   6
#define M0   (BB*SS)       // 8192 tokens
#define NBA  (BB*NHH)      // 192 attention batches
#define H3   (3*HH)        // 2304

// ---------------------------------------------------------------------------
// Scratch buffers (activations as bf16 hi/lo pairs; T/T2 fp32 for LayerNorm)
// ---------------------------------------------------------------------------
__device__ __nv_bfloat16 g_XH[M0*HH],   g_XL[M0*HH];
__device__ __nv_bfloat16 g_QKVH[M0*H3], g_QKVL[M0*H3];
__device__ __nv_bfloat16 g_CH[M0*HH],   g_CL[M0*HH];
__device__ __nv_bfloat16 g_AH[M0*HH],   g_AL[M0*HH];
__device__ __nv_bfloat16 g_IH[M0*II],   g_IL[M0*II];
__device__ float g_T[M0*HH];
__device__ float g_T2[M0*HH];           // split-K second-half partial
// pre-split bf16 weights (hi/lo), original [K][N] layout
__device__ __nv_bfloat16 g_WqkvH[LL*HH*H3], g_WqkvL[LL*HH*H3];
__device__ __nv_bfloat16 g_WoH[LL*HH*HH],   g_WoL[LL*HH*HH];
__device__ __nv_bfloat16 g_WiH[LL*HH*II],   g_WiL[LL*HH*II];
__device__ __nv_bfloat16 g_Wo2H[LL*II*HH],  g_Wo2L[LL*II*HH];
__device__ float g_bqkv[LL*H3];

// ---------------------------------------------------------------------------
// PTX helpers
// ---------------------------------------------------------------------------
__device__ __forceinline__ uint32_t smem_u32(const void* p) {
    return (uint32_t)__cvta_generic_to_shared(p);
}
__device__ __forceinline__ void ldsm_x4(uint32_t* r, uint32_t a) {
    asm volatile("ldmatrix.sync.aligned.m8n8.x4.shared.b16 {%0,%1,%2,%3}, [%4];"
        : "=r"(r[0]), "=r"(r[1]), "=r"(r[2]), "=r"(r[3]) : "r"(a));
}
__device__ __forceinline__ void ldsm_x4t(uint32_t* r, uint32_t a) {
    asm volatile("ldmatrix.sync.aligned.m8n8.x4.trans.shared.b16 {%0,%1,%2,%3}, [%4];"
        : "=r"(r[0]), "=r"(r[1]), "=r"(r[2]), "=r"(r[3]) : "r"(a));
}
__device__ __forceinline__ void mma16816(float* c, const uint32_t* a, const uint32_t* b) {
    asm volatile(
        "mma.sync.aligned.m16n8k16.row.col.f32.bf16.bf16.f32 "
        "{%0,%1,%2,%3}, {%4,%5,%6,%7}, {%8,%9}, {%0,%1,%2,%3};"
        : "+f"(c[0]), "+f"(c[1]), "+f"(c[2]), "+f"(c[3])
        : "r"(a[0]), "r"(a[1]), "r"(a[2]), "r"(a[3]), "r"(b[0]), "r"(b[1]));
}
#define CP_ASYNC16(dst, src) \
    asm volatile("cp.async.cg.shared.global [%0], [%1], 16;" :: "r"(dst), "l"(src) : "memory")
#define CP_COMMIT() asm volatile("cp.async.commit_group;" ::: "memory")
#define CP_WAIT1()  asm volatile("cp.async.wait_group 1;" ::: "memory")

// fp32 -> (bf16 hi, bf16 lo) exact-residual split
__device__ __forceinline__ void split1(float x, unsigned short& hi, unsigned short& lo) {
    __nv_bfloat16 h = __float2bfloat16(x);
    hi = *reinterpret_cast<unsigned short*>(&h);
    float r = x - __bfloat162float(h);
    __nv_bfloat16 l = __float2bfloat16(r);
    lo = *reinterpret_cast<unsigned short*>(&l);
}
__device__ __forceinline__ void split4(float4 v, ushort4& hi, ushort4& lo) {
    split1(v.x, hi.x, lo.x);
    split1(v.y, hi.y, lo.y);
    split1(v.z, hi.z, lo.z);
    split1(v.w, hi.w, lo.w);
}
__device__ __forceinline__ float bf2f(unsigned short u) {
    __nv_bfloat16 h = *reinterpret_cast<__nv_bfloat16*>(&u);
    return __bfloat162float(h);
}

// ---------------------------------------------------------------------------
// Preprocessing: ALL weight splits in ONE launch (blockIdx.z selects matrix)
// ---------------------------------------------------------------------------
__global__ void split_all(const float* __restrict__ Wq, const float* __restrict__ Wk,
                          const float* __restrict__ Wv, const float* __restrict__ Wo,
                          const float* __restrict__ Wi, const float* __restrict__ Wo2,
                          __nv_bfloat16* __restrict__ WqkvH, __nv_bfloat16* __restrict__ WqkvL,
                          __nv_bfloat16* __restrict__ WoH,   __nv_bfloat16* __restrict__ WoL,
                          __nv_bfloat16* __restrict__ WiH,   __nv_bfloat16* __restrict__ WiL,
                          __nv_bfloat16* __restrict__ Wo2H,  __nv_bfloat16* __restrict__ Wo2L)
{
    const int l = blockIdx.y;
    const float* src; __nv_bfloat16 *dh, *dl;
    int R, Cc, outC, colOff;
    switch (blockIdx.z) {
        case 0: src = Wq;  dh = WqkvH; dl = WqkvL; R = HH; Cc = HH; outC = H3; colOff = 0;    break;
        case 1: src = Wk;  dh = WqkvH; dl = WqkvL; R = HH; Cc = HH; outC = H3; colOff = HH;   break;
        case 2: src = Wv;  dh = WqkvH; dl = WqkvL; R = HH; Cc = HH; outC = H3; colOff = 2*HH; break;
        case 3: src = Wo;  dh = WoH;   dl = WoL;   R = HH; Cc = HH; outC = HH; colOff = 0;    break;
        case 4: src = Wi;  dh = WiH;   dl = WiL;   R = HH; Cc = II; outC = II; colOff = 0;    break;
        default:src = Wo2; dh = Wo2H;  dl = Wo2L;  R = II; Cc = HH; outC = HH; colOff = 0;    break;
    }
    int id = blockIdx.x*256 + threadIdx.x;
    if (id >= R*Cc/4) return;
    int r = id / (Cc/4), c4 = id % (Cc/4);
    float4 v = *(const float4*)(src + (size_t)l*R*Cc + (size_t)r*Cc + c4*4);
    ushort4 hi, lo; split4(v, hi, lo);
    *(ushort4*)(dh + (size_t)l*R*outC + (size_t)r*outC + colOff + c4*4) = hi;
    *(ushort4*)(dl + (size_t)l*R*outC + (size_t)r*outC + colOff + c4*4) = lo;
}

__global__ void concat_bias(const float* __restrict__ bq, const float* __restrict__ bk,
                            const float* __restrict__ bv, float* __restrict__ dst)
{
    int id = blockIdx.x*256 + threadIdx.x;
    if (id >= LL*HH) return;
    int l = id / HH, c = id % HH;
    dst[(size_t)l*H3 + c]        = bq[id];
    dst[(size_t)l*H3 + HH + c]   = bk[id];
    dst[(size_t)l*H3 + 2*HH + c] = bv[id];
}

__global__ void split_x(const float* __restrict__ src,
                        __nv_bfloat16* __restrict__ dh,
                        __nv_bfloat16* __restrict__ dl, int n4)
{
    int id = blockIdx.x*256 + threadIdx.x;
    if (id >= n4) return;
    float4 v = *(const float4*)(src + (size_t)id*4);
    ushort4 hi, lo; split4(v, hi, lo);
    *(ushort4*)(dh + (size_t)id*4) = hi;
    *(ushort4*)(dl + (size_t)id*4) = lo;
}

// ---------------------------------------------------------------------------
// bf16x3 GEMM, all-bf16 via cp.async, 3-stage pipeline, 2 CTAs/SM.
// Block tile 128x128xK. If SPLITK: gridDim.z=2, each z computes half of K
// (K param = per-CTA half-K); z=0 -> EPI path into Cf, z=1 -> plain into Cf2.
// EPI: 0 = bias -> split out; 1 = bias + residual -> fp32; 2 = bias+GELU -> split
// ---------------------------------------------------------------------------
#define LAS   40            // A row stride (shorts): 32 + 8 pad
#define LBS   136           // B row stride (shorts): 128 + 8 pad
#define ASZ   (128*LAS)
#define BSZ   (32*LBS)
#define STG   (2*ASZ + 2*BSZ)
#define GEMM_SMEM (3*STG*2)            // 113664 B

template<int EPI, int SPLITK>
__global__ void __launch_bounds__(256, 2)
gemm_cp(const __nv_bfloat16* __restrict__ AH, const __nv_bfloat16* __restrict__ AL, int lda,
        const __nv_bfloat16* __restrict__ BH, const __nv_bfloat16* __restrict__ BL, int ldb,
        const float* __restrict__ bias,
        const __nv_bfloat16* __restrict__ RH, const __nv_bfloat16* __restrict__ RL, int ldr,
        float* __restrict__ Cf, float* __restrict__ Cf2,
        __nv_bfloat16* __restrict__ CH, __nv_bfloat16* __restrict__ CL,
        int ldc, int K)
{
    extern __shared__ __align__(16) unsigned short sm[];
    const uint32_t smb = smem_u32(sm);

    const int tid = threadIdx.x, lane = tid & 31, wid = tid >> 5;
    const int wm = wid >> 1, wn = wid & 1;          // 4x2 warp grid, tile 32x64
    const int m0 = blockIdx.y * 128, n0 = blockIdx.x * 128;

    if (SPLITK) {                                   // K-half offset for z=1
        const size_t koff = (size_t)blockIdx.z * K;
        AH += koff; AL += koff;
        BH += koff * ldb; BL += koff * ldb;
    }

    float acc[2][8][4] = {};

    auto issue = [&](int st, int k0) {
        const uint32_t base = smb + st*STG*2;
        #pragma unroll
        for (int it = 0; it < 2; ++it) {
            int id = tid + it*256;
            int r = id >> 2, cc = id & 3;                       // A: 4 chunks/row
            uint32_t d = base + (uint32_t)(r*LAS + cc*8)*2;
            const size_t off = (size_t)(m0+r)*lda + k0 + cc*8;
            CP_ASYNC16(d,         AH + off);
            CP_ASYNC16(d + ASZ*2, AL + off);
        }
        #pragma unroll
        for (int it = 0; it < 2; ++it) {
            int id = tid + it*256;
            int r = id >> 4, cc = id & 15;                      // B: 16 chunks/row
            uint32_t d = base + 2*ASZ*2 + (uint32_t)(r*LBS + cc*8)*2;
            const size_t off = (size_t)(k0+r)*ldb + n0 + cc*8;
            CP_ASYNC16(d,         BH + off);
            CP_ASYNC16(d + BSZ*2, BL + off);
        }
    };

    const int nk = K / 32;
    issue(0, 0);  CP_COMMIT();
    issue(1, 32); CP_COMMIT();

    for (int kt = 0; kt < nk; ++kt) {
        CP_WAIT1();
        __syncthreads();
        if (kt + 2 < nk) issue((kt+2) % 3, (kt+2)*32);
        CP_COMMIT();

        const unsigned short* Ah = sm + (kt%3)*STG;
        const unsigned short* Al = Ah + ASZ;
        const unsigned short* Bh = Al + ASZ;
        const unsigned short* Bl = Bh + BSZ;

        #pragma unroll
        for (int ks = 0; ks < 2; ++ks) {
            uint32_t ah[2][4], al[2][4];
            #pragma unroll
            for (int mt = 0; mt < 2; ++mt) {
                int r = wm*32 + mt*16 + (lane & 15);
                int c = ks*16 + ((lane >> 4) << 3);
                ldsm_x4(ah[mt], smem_u32(Ah + r*LAS + c));
                ldsm_x4(al[mt], smem_u32(Al + r*LAS + c));
            }
            #pragma unroll
            for (int np = 0; np < 4; ++np) {
                uint32_t bh[4], bl[4];
                int off = (ks*16 + (lane & 15))*LBS + wn*64 + np*16 + ((lane >> 4) << 3);
                ldsm_x4t(bh, smem_u32(Bh + off));
                ldsm_x4t(bl, smem_u32(Bl + off));
                #pragma unroll
                for (int s = 0; s < 2; ++s)
                    #pragma unroll
                    for (int mt = 0; mt < 2; ++mt)
                        mma16816(acc[mt][np*2+s], ah[mt], bh + s*2);
                #pragma unroll
                for (int s = 0; s < 2; ++s)
                    #pragma unroll
                    for (int mt = 0; mt < 2; ++mt)
                        mma16816(acc[mt][np*2+s], al[mt], bh + s*2);
                #pragma unroll
                for (int s = 0; s < 2; ++s)
                    #pragma unroll
                    for (int mt = 0; mt < 2; ++mt)
                        mma16816(acc[mt][np*2+s], ah[mt], bl + s*2);
            }
        }
    }

    // --- epilogue ---
    const bool plain = SPLITK && (blockIdx.z == 1);   // second K-half: raw partial
    #pragma unroll
    for (int mt = 0; mt < 2; ++mt) {
        #pragma unroll
        for (int nt = 0; nt < 8; ++nt) {
            const int row = m0 + wm*32 + mt*16 + (lane >> 2);
            const int col = n0 + wn*64 + nt*8 + (lane & 3)*2;
            #pragma unroll
            for (int h = 0; h < 2; ++h) {
                const int r2 = row + h*8;
                float v0 = acc[mt][nt][h*2+0];
                float v1 = acc[mt][nt][h*2+1];
                if (plain) {
                    *(float2*)(Cf2 + (size_t)r2*ldc + col) = make_float2(v0, v1);
                    continue;
                }
                v0 += bias[col]; v1 += bias[col+1];
                if (EPI == 1) {
                    const size_t ri = (size_t)r2*ldr + col;
                    const ushort2 rh = *(const ushort2*)(RH + ri);
                    const ushort2 rl = *(const ushort2*)(RL + ri);
                    v0 += bf2f(rh.x) + bf2f(rl.x);
                    v1 += bf2f(rh.y) + bf2f(rl.y);
                    *(float2*)(Cf + (size_t)r2*ldc + col) = make_float2(v0, v1);
                } else {
                    if (EPI == 2) {
                        v0 = 0.5f*v0*(1.0f + erff(v0 * 0.70710678118654752f));
                        v1 = 0.5f*v1*(1.0f + erff(v1 * 0.70710678118654752f));
                    }
                    unsigned short h0, l0, h1, l1;
                    split1(v0, h0, l0); split1(v1, h1, l1);
                    const size_t ci = (size_t)r2*ldc + col;
                    *(ushort2*)(CH + ci) = make_ushort2(h0, h1);
                    *(ushort2*)(CL + ci) = make_ushort2(l0, l1);
                }
            }
        }
    }
}

// ---------------------------------------------------------------------------
// Fused flash attention; Q/K/V pre-split bf16 (ld = H3); ctx out as hi/lo.
// ---------------------------------------------------------------------------
#define FLASH_SMEM (6*128*(64+8)*2)   // 110592 B

__global__ void __launch_bounds__(256, 1)
flash_attn(const __nv_bfloat16* __restrict__ QKVH,
           const __nv_bfloat16* __restrict__ QKVL,
           __nv_bfloat16* __restrict__ OH, __nv_bfloat16* __restrict__ OL)
{
    constexpr int DP  = DHH + 8;
    constexpr int QSZ = 128*DP;

    extern __shared__ __align__(16) unsigned short dynsm[];
    unsigned short* Qh = dynsm;
    unsigned short* Ql = Qh + QSZ;
    unsigned short* Kh = Ql + QSZ;
    unsigned short* Kl = Kh + QSZ;
    unsigned short* Vh = Kl + QSZ;
    unsigned short* Vl = Vh + QSZ;

    const int tid = threadIdx.x, lane = tid & 31, w = tid >> 5;
    const int b = blockIdx.y / NHH, hh = blockIdx.y % NHH;
    const int q0 = blockIdx.x * 128;
    const size_t qoff = ((size_t)b*SS + q0)*H3 + hh*DHH;
    const size_t koff = (size_t)b*SS*H3 + HH + hh*DHH;
    const size_t voff = (size_t)b*SS*H3 + 2*HH + hh*DHH;

    #pragma unroll
    for (int it = 0; it < 4; ++it) {
        int id = tid + it*256;
        int r = id >> 3, c8 = id & 7;
        *(uint4*)&Qh[r*DP + c8*8] = *(const uint4*)(QKVH + qoff + (size_t)r*H3 + c8*8);
        *(uint4*)&Ql[r*DP + c8*8] = *(const uint4*)(QKVL + qoff + (size_t)r*H3 + c8*8);
    }
    __syncthreads();

    uint32_t qh[4][4], ql[4][4];
    {
        int r = w*16 + (lane & 15);
        #pragma unroll
        for (int ks = 0; ks < 4; ++ks) {
            int c = ks*16 + ((lane >> 4) << 3);
            ldsm_x4(qh[ks], smem_u32(Qh + r*DP + c));
            ldsm_x4(ql[ks], smem_u32(Ql + r*DP + c));
        }
    }

    float oacc[8][4] = {};
    float mrow[2] = {-1e30f, -1e30f};
    float lrow[2] = {0.0f, 0.0f};

    const int kb_row = (lane & 7) + ((lane & 16) >> 1);
    const int kb_col = ((lane >> 3) & 1) * 8;

    for (int j = 0; j < 4; ++j) {
        const size_t s0 = (size_t)j*128;
        #pragma unroll
        for (int it = 0; it < 4; ++it) {
            int id = tid + it*256;
            int r = id >> 3, c8 = id & 7;
            const size_t gk = koff + (s0+r)*H3 + c8*8;
            const size_t gv = voff + (s0+r)*H3 + c8*8;
            *(uint4*)&Kh[r*DP + c8*8] = *(const uint4*)(QKVH + gk);
            *(uint4*)&Kl[r*DP + c8*8] = *(const uint4*)(QKVL + gk);
            *(uint4*)&Vh[r*DP + c8*8] = *(const uint4*)(QKVH + gv);
            *(uint4*)&Vl[r*DP + c8*8] = *(const uint4*)(QKVL + gv);
        }
        __syncthreads();

        float sacc[16][4] = {};
        #pragma unroll
        for (int ks = 0; ks < 4; ++ks) {
            #pragma unroll
            for (int np = 0; np < 8; ++np) {
                uint32_t bh[4], bl[4];
                int off = (np*16 + kb_row)*DP + ks*16 + kb_col;
                ldsm_x4(bh, smem_u32(Kh + off));
                ldsm_x4(bl, smem_u32(Kl + off));
                #pragma unroll
                for (int s = 0; s < 2; ++s) mma16816(sacc[np*2+s], qh[ks], bh + s*2);
                #pragma unroll
                for (int s = 0; s < 2; ++s) mma16816(sacc[np*2+s], ql[ks], bh + s*2);
                #pragma unroll
                for (int s = 0; s < 2; ++s) mma16816(sacc[np*2+s], qh[ks], bl + s*2);
            }
        }
        #pragma unroll
        for (int nt = 0; nt < 16; ++nt) {
            sacc[nt][0] *= 0.125f; sacc[nt][1] *= 0.125f;
            sacc[nt][2] *= 0.125f; sacc[nt][3] *= 0.125f;
        }

        #pragma unroll
        for (int h = 0; h < 2; ++h) {
            float mx = -1e30f;
            #pragma unroll
            for (int nt = 0; nt < 16; ++nt)
                mx = fmaxf(mx, fmaxf(sacc[nt][2*h], sacc[nt][2*h+1]));
            mx = fmaxf(mx, __shfl_xor_sync(0xffffffffu, mx, 1));
            mx = fmaxf(mx, __shfl_xor_sync(0xffffffffu, mx, 2));
            float mnew = fmaxf(mrow[h], mx);
            float corr = expf(mrow[h] - mnew);
            mrow[h] = mnew;
            float sum = 0.0f;
            #pragma unroll
            for (int nt = 0; nt < 16; ++nt) {
                float p0 = expf(sacc[nt][2*h]   - mnew);
                float p1 = expf(sacc[nt][2*h+1] - mnew);
                sacc[nt][2*h] = p0; sacc[nt][2*h+1] = p1;
                sum += p0 + p1;
            }
            sum += __shfl_xor_sync(0xffffffffu, sum, 1);
            sum += __shfl_xor_sync(0xffffffffu, sum, 2);
            lrow[h] = lrow[h]*corr + sum;
            #pragma unroll
            for (int nt = 0; nt < 8; ++nt) {
                oacc[nt][2*h]   *= corr;
                oacc[nt][2*h+1] *= corr;
            }
        }

        #pragma unroll
        for (int ks = 0; ks < 8; ++ks) {
            uint32_t ph[4], pl[4];
            #pragma unroll
            for (int q = 0; q < 2; ++q) {
                #pragma unroll
                for (int hf = 0; hf < 2; ++hf) {
                    float x = sacc[2*ks+q][2*hf];
                    float y = sacc[2*ks+q][2*hf+1];
                    unsigned short hx, lx, hy, ly;
                    split1(x, hx, lx); split1(y, hy, ly);
                    ph[2*q+hf] = (uint32_t)hx | ((uint32_t)hy << 16);
                    pl[2*q+hf] = (uint32_t)lx | ((uint32_t)ly << 16);
                }
            }
            #pragma unroll
            for (int np = 0; np < 4; ++np) {
                uint32_t bh[4], bl[4];
                int off = (ks*16 + (lane & 15))*DP + np*16 + ((lane >> 4) << 3);
                ldsm_x4t(bh, smem_u32(Vh + off));
                ldsm_x4t(bl, smem_u32(Vl + off));
                #pragma unroll
                for (int s = 0; s < 2; ++s) mma16816(oacc[np*2+s], ph, bh + s*2);
                #pragma unroll
                for (int s = 0; s < 2; ++s) mma16816(oacc[np*2+s], pl, bh + s*2);
                #pragma unroll
                for (int s = 0; s < 2; ++s) mma16816(oacc[np*2+s], ph, bl + s*2);
            }
        }
        __syncthreads();
    }

    const size_t obase = (size_t)b*SS*HH + (size_t)hh*DHH;
    const int orow = w*16 + (lane >> 2);
    #pragma unroll
    for (int h = 0; h < 2; ++h) {
        const float inv = 1.0f / lrow[h];
        const int r = q0 + orow + h*8;
        #pragma unroll
        for (int nt = 0; nt < 8; ++nt) {
            const int c = nt*8 + (lane & 3)*2;
            unsigned short h0, l0, h1, l1;
            split1(oacc[nt][2*h]*inv,   h0, l0);
            split1(oacc[nt][2*h+1]*inv, h1, l1);
            const size_t oi = obase + (size_t)r*HH + c;
            *(ushort2*)(OH + oi) = make_ushort2(h0, h1);
            *(ushort2*)(OL + oi) = make_ushort2(l0, l1);
        }
    }
}

// ---------------------------------------------------------------------------
// LayerNorm (warp per row). ADD2: sum X + X2 (split-K partial merge).
// SPLIT=1 -> bf16 hi/lo out; SPLIT=0 -> fp32 out.
// ---------------------------------------------------------------------------
template<int SPLIT>
__global__ void layernorm768(const float* __restrict__ X,
                             const float* __restrict__ X2,
                             const float* __restrict__ g,
                             const float* __restrict__ b,
                             float* __restrict__ Yf,
                             __nv_bfloat16* __restrict__ YH,
                             __nv_bfloat16* __restrict__ YL, int rows)
{
    const int warp = (blockIdx.x * blockDim.x + threadIdx.x) >> 5;
    const int lane = threadIdx.x & 31;
    if (warp >= rows) return;
    const float4* x  = (const float4*)(X  + (size_t)warp * 768);
    const float4* x2 = (const float4*)(X2 + (size_t)warp * 768);

    float4 v[6];
    float s = 0.0f;
    #pragma unroll
    for (int i = 0; i < 6; ++i) {
        float4 a = x[lane + i*32];
        float4 c = x2[lane + i*32];
        v[i] = make_float4(a.x + c.x, a.y + c.y, a.z + c.z, a.w + c.w);
        s += v[i].x + v[i].y + v[i].z + v[i].w;
    }
    #pragma unroll
    for (int o = 16; o; o >>= 1) s += __shfl_xor_sync(0xffffffffu, s, o);
    const float mean = s * (1.0f / 768.0f);

    float var = 0.0f;
    #pragma unroll
    for (int i = 0; i < 6; ++i) {
        float dx = v[i].x - mean, dy = v[i].y - mean, dz = v[i].z - mean, dw = v[i].w - mean;
        var += dx*dx + dy*dy + dz*dz + dw*dw;
    }
    #pragma unroll
    for (int o = 16; o; o >>= 1) var += __shfl_xor_sync(0xffffffffu, var, o);
    const float rs = rsqrtf(var * (1.0f / 768.0f) + 1e-12f);

    const float4* gg = (const float4*)g;
    const float4* bb = (const float4*)b;
    #pragma unroll
    for (int i = 0; i < 6; ++i) {
        const int c = lane + i*32;
        const float4 gv = gg[c], bv = bb[c];
        float4 o4;
        o4.x = (v[i].x - mean) * rs * gv.x + bv.x;
        o4.y = (v[i].y - mean) * rs * gv.y + bv.y;
        o4.z = (v[i].z - mean) * rs * gv.z + bv.z;
        o4.w = (v[i].w - mean) * rs * gv.w + bv.w;
        if (SPLIT) {
            ushort4 hi, lo; split4(o4, hi, lo);
            *(ushort4*)(YH + (size_t)warp*768 + c*4) = hi;
            *(ushort4*)(YL + (size_t)warp*768 + c*4) = lo;
        } else {
            *(float4*)(Yf + (size_t)warp*768 + c*4) = o4;
        }
    }
}

// ---------------------------------------------------------------------------
// Launch
// ---------------------------------------------------------------------------
extern "C" void kernel_launch(void* const* d_in, const int* in_sizes, int n_in,
                              void* d_out, int out_size)
{
    (void)in_sizes; (void)n_in; (void)out_size;
    const float* hs  = (const float*)d_in[0];
    const float* Wq  = (const float*)d_in[1];  const float* bq  = (const float*)d_in[2];
    const float* Wk  = (const float*)d_in[3];  const float* bk  = (const float*)d_in[4];
    const float* Wv  = (const float*)d_in[5];  const float* bv  = (const float*)d_in[6];
    const float* Wo  = (const float*)d_in[7];  const float* bo  = (const float*)d_in[8];
    const float* g1  = (const float*)d_in[9];  const float* b1  = (const float*)d_in[10];
    const float* Wi  = (const float*)d_in[11]; const float* bi  = (const float*)d_in[12];
    const float* Wo2 = (const float*)d_in[13]; const float* bo2 = (const float*)d_in[14];
    const float* g2  = (const float*)d_in[15]; const float* b2  = (const float*)d_in[16];

    __nv_bfloat16 *XH, *XL, *QKVH, *QKVL, *CH, *CL, *AH, *AL, *IH, *IL;
    __nv_bfloat16 *WqkvH, *WqkvL, *WoH, *WoL, *WiH, *WiL, *Wo2H, *Wo2L;
    float *T, *T2, *bqkv;
    cudaGetSymbolAddress((void**)&XH, g_XH);   cudaGetSymbolAddress((void**)&XL, g_XL);
    cudaGetSymbolAddress((void**)&QKVH, g_QKVH); cudaGetSymbolAddress((void**)&QKVL, g_QKVL);
    cudaGetSymbolAddress((void**)&CH, g_CH);   cudaGetSymbolAddress((void**)&CL, g_CL);
    cudaGetSymbolAddress((void**)&AH, g_AH);   cudaGetSymbolAddress((void**)&AL, g_AL);
    cudaGetSymbolAddress((void**)&IH, g_IH);   cudaGetSymbolAddress((void**)&IL, g_IL);
    cudaGetSymbolAddress((void**)&T,  g_T);    cudaGetSymbolAddress((void**)&T2, g_T2);
    cudaGetSymbolAddress((void**)&bqkv, g_bqkv);
    cudaGetSymbolAddress((void**)&WqkvH, g_WqkvH); cudaGetSymbolAddress((void**)&WqkvL, g_WqkvL);
    cudaGetSymbolAddress((void**)&WoH, g_WoH); cudaGetSymbolAddress((void**)&WoL, g_WoL);
    cudaGetSymbolAddress((void**)&WiH, g_WiH); cudaGetSymbolAddress((void**)&WiL, g_WiL);
    cudaGetSymbolAddress((void**)&Wo2H, g_Wo2H); cudaGetSymbolAddress((void**)&Wo2L, g_Wo2L);

    cudaFuncSetAttribute((const void*)gemm_cp<0,0>, cudaFuncAttributeMaxDynamicSharedMemorySize, GEMM_SMEM);
    cudaFuncSetAttribute((const void*)gemm_cp<1,1>, cudaFuncAttributeMaxDynamicSharedMemorySize, GEMM_SMEM);
    cudaFuncSetAttribute((const void*)gemm_cp<2,0>, cudaFuncAttributeMaxDynamicSharedMemorySize, GEMM_SMEM);
    cudaFuncSetAttribute((const void*)flash_attn, cudaFuncAttributeMaxDynamicSharedMemorySize, FLASH_SMEM);

    // --- preprocessing ---
    split_all<<<dim3(HH*II/1024, LL, 6), 256>>>(Wq, Wk, Wv, Wo, Wi, Wo2,
        WqkvH, WqkvL, WoH, WoL, WiH, WiL, Wo2H, Wo2L);
    concat_bias<<<(LL*HH + 255)/256, 256>>>(bq, bk, bv, bqkv);
    split_x<<<(M0*HH/4 + 255)/256, 256>>>(hs, XH, XL, M0*HH/4);

    for (int l = 0; l < LL; ++l) {
        const __nv_bfloat16* wqkvH = WqkvH + (size_t)l*HH*H3;
        const __nv_bfloat16* wqkvL = WqkvL + (size_t)l*HH*H3;
        const __nv_bfloat16* woH   = WoH   + (size_t)l*HH*HH;
        const __nv_bfloat16* woL   = WoL   + (size_t)l*HH*HH;
        const __nv_bfloat16* wiH   = WiH   + (size_t)l*HH*II;
        const __nv_bfloat16* wiL   = WiL   + (size_t)l*HH*II;
        const __nv_bfloat16* wo2H  = Wo2H  + (size_t)l*II*HH;
        const __nv_bfloat16* wo2L  = Wo2L  + (size_t)l*II*HH;
        const float* bqkvl = bqkv + (size_t)l*H3;
        const float* bol   = bo   + (size_t)l*HH;
        const float* bil   = bi   + (size_t)l*II;
        const float* bo2l  = bo2  + (size_t)l*HH;

        // QKV projection (N=2304, 1152 tiles: good wave quantization)
        gemm_cp<0,0><<<dim3(H3/128, M0/128), 256, GEMM_SMEM>>>(
            XH, XL, HH, wqkvH, wqkvL, H3, bqkvl,
            nullptr, nullptr, 0, nullptr, nullptr, QKVH, QKVL, H3, HH);

        // fused attention -> ctx (hi/lo)
        flash_attn<<<dim3(SS/128, NBA), 256, FLASH_SMEM>>>(QKVH, QKVL, CH, CL);

        // O projection + residual(X): SPLIT-K=2 (768 CTAs of K=384)
        // z=0 -> T (bias+residual), z=1 -> T2 (raw partial); LN sums them.
        gemm_cp<1,1><<<dim3(HH/128, M0/128, 2), 256, GEMM_SMEM>>>(
            CH, CL, HH, woH, woL, HH, bol,
            XH, XL, HH, T, T2, nullptr, nullptr, HH, HH/2);
        layernorm768<1><<<M0/8, 256>>>(T, T2, g1 + (size_t)l*HH, b1 + (size_t)l*HH,
                                       nullptr, AH, AL, M0);

        // FFN1: I = gelu(A @ Wi + bi)  (N=3072, 1536 tiles)
        gemm_cp<2,0><<<dim3(II/128, M0/128), 256, GEMM_SMEM>>>(
            AH, AL, HH, wiH, wiL, II, bil,
            nullptr, nullptr, 0, nullptr, nullptr, IH, IL, II, HH);

        // FFN2 + residual(A): SPLIT-K=2 (768 CTAs of K=1536)
        gemm_cp<1,1><<<dim3(HH/128, M0/128, 2), 256, GEMM_SMEM>>>(
            IH, IL, II, wo2H, wo2L, HH, bo2l,
            AH, AL, HH, T, T2, nullptr, nullptr, HH, II/2);

        if (l == LL-1) {
            layernorm768<0><<<M0/8, 256>>>(T, T2, g2 + (size_t)l*HH, b2 + (size_t)l*HH,
                                           (float*)d_out, nullptr, nullptr, M0);
        } else {
            layernorm768<1><<<M0/8, 256>>>(T, T2, g2 + (size_t)l*HH, b2 + (size_t)l*HH,
                                           nullptr, XH, XL, M0);
        }
    }
}

// round 14
// speedup vs baseline: 1.0767x; 1.0364x over previous
#include <cuda_runtime.h>
#include <cuda_bf16.h>
#include <math.h>
#include <stdint.h>

// Problem constants
#define BB   16
#define SS   512
#define HH   768
#define II   3072
#define NHH  12
#define DHH  64
#define LL   6
#define M0   (BB*SS)       // 8192 tokens
#define NBA  (BB*NHH)      // 192 attention batches
#define H3   (3*HH)        // 2304

// ---------------------------------------------------------------------------
// Scratch buffers (activations as bf16 hi/lo pairs; T/T2 fp32 for LayerNorm)
// ---------------------------------------------------------------------------
__device__ __nv_bfloat16 g_XH[M0*HH],   g_XL[M0*HH];
__device__ __nv_bfloat16 g_QKVH[M0*H3], g_QKVL[M0*H3];
__device__ __nv_bfloat16 g_CH[M0*HH],   g_CL[M0*HH];
__device__ __nv_bfloat16 g_AH[M0*HH],   g_AL[M0*HH];
__device__ __nv_bfloat16 g_IH[M0*II],   g_IL[M0*II];
__device__ float g_T[M0*HH];
__device__ float g_T2[M0*HH];
// pre-split bf16 weights (hi/lo), original [K][N] layout
__device__ __nv_bfloat16 g_WqkvH[LL*HH*H3], g_WqkvL[LL*HH*H3];
__device__ __nv_bfloat16 g_WoH[LL*HH*HH],   g_WoL[LL*HH*HH];
__device__ __nv_bfloat16 g_WiH[LL*HH*II],   g_WiL[LL*HH*II];
__device__ __nv_bfloat16 g_Wo2H[LL*II*HH],  g_Wo2L[LL*II*HH];
__device__ float g_bqkv[LL*H3];

// ---------------------------------------------------------------------------
// PTX helpers
// ---------------------------------------------------------------------------
__device__ __forceinline__ uint32_t smem_u32(const void* p) {
    return (uint32_t)__cvta_generic_to_shared(p);
}
__device__ __forceinline__ void ldsm_x4(uint32_t* r, uint32_t a) {
    asm volatile("ldmatrix.sync.aligned.m8n8.x4.shared.b16 {%0,%1,%2,%3}, [%4];"
        : "=r"(r[0]), "=r"(r[1]), "=r"(r[2]), "=r"(r[3]) : "r"(a));
}
__device__ __forceinline__ void ldsm_x4t(uint32_t* r, uint32_t a) {
    asm volatile("ldmatrix.sync.aligned.m8n8.x4.trans.shared.b16 {%0,%1,%2,%3}, [%4];"
        : "=r"(r[0]), "=r"(r[1]), "=r"(r[2]), "=r"(r[3]) : "r"(a));
}
__device__ __forceinline__ void mma16816(float* c, const uint32_t* a, const uint32_t* b) {
    asm volatile(
        "mma.sync.aligned.m16n8k16.row.col.f32.bf16.bf16.f32 "
        "{%0,%1,%2,%3}, {%4,%5,%6,%7}, {%8,%9}, {%0,%1,%2,%3};"
        : "+f"(c[0]), "+f"(c[1]), "+f"(c[2]), "+f"(c[3])
        : "r"(a[0]), "r"(a[1]), "r"(a[2]), "r"(a[3]), "r"(b[0]), "r"(b[1]));
}
#define CP_ASYNC16(dst, src) \
    asm volatile("cp.async.cg.shared.global [%0], [%1], 16;" :: "r"(dst), "l"(src) : "memory")
#define CP_COMMIT() asm volatile("cp.async.commit_group;" ::: "memory")
#define CP_WAIT2()  asm volatile("cp.async.wait_group 2;" ::: "memory")

// fp32 -> (bf16 hi, bf16 lo) exact-residual split
__device__ __forceinline__ void split1(float x, unsigned short& hi, unsigned short& lo) {
    __nv_bfloat16 h = __float2bfloat16(x);
    hi = *reinterpret_cast<unsigned short*>(&h);
    float r = x - __bfloat162float(h);
    __nv_bfloat16 l = __float2bfloat16(r);
    lo = *reinterpret_cast<unsigned short*>(&l);
}
__device__ __forceinline__ void split4(float4 v, ushort4& hi, ushort4& lo) {
    split1(v.x, hi.x, lo.x);
    split1(v.y, hi.y, lo.y);
    split1(v.z, hi.z, lo.z);
    split1(v.w, hi.w, lo.w);
}
__device__ __forceinline__ float bf2f(unsigned short u) {
    __nv_bfloat16 h = *reinterpret_cast<__nv_bfloat16*>(&u);
    return __bfloat162float(h);
}

// ---------------------------------------------------------------------------
// Preprocessing
// ---------------------------------------------------------------------------
__global__ void split_all(const float* __restrict__ Wq, const float* __restrict__ Wk,
                          const float* __restrict__ Wv, const float* __restrict__ Wo,
                          const float* __restrict__ Wi, const float* __restrict__ Wo2,
                          __nv_bfloat16* __restrict__ WqkvH, __nv_bfloat16* __restrict__ WqkvL,
                          __nv_bfloat16* __restrict__ WoH,   __nv_bfloat16* __restrict__ WoL,
                          __nv_bfloat16* __restrict__ WiH,   __nv_bfloat16* __restrict__ WiL,
                          __nv_bfloat16* __restrict__ Wo2H,  __nv_bfloat16* __restrict__ Wo2L)
{
    const int l = blockIdx.y;
    const float* src; __nv_bfloat16 *dh, *dl;
    int R, Cc, outC, colOff;
    switch (blockIdx.z) {
        case 0: src = Wq;  dh = WqkvH; dl = WqkvL; R = HH; Cc = HH; outC = H3; colOff = 0;    break;
        case 1: src = Wk;  dh = WqkvH; dl = WqkvL; R = HH; Cc = HH; outC = H3; colOff = HH;   break;
        case 2: src = Wv;  dh = WqkvH; dl = WqkvL; R = HH; Cc = HH; outC = H3; colOff = 2*HH; break;
        case 3: src = Wo;  dh = WoH;   dl = WoL;   R = HH; Cc = HH; outC = HH; colOff = 0;    break;
        case 4: src = Wi;  dh = WiH;   dl = WiL;   R = HH; Cc = II; outC = II; colOff = 0;    break;
        default:src = Wo2; dh = Wo2H;  dl = Wo2L;  R = II; Cc = HH; outC = HH; colOff = 0;    break;
    }
    int id = blockIdx.x*256 + threadIdx.x;
    if (id >= R*Cc/4) return;
    int r = id / (Cc/4), c4 = id % (Cc/4);
    float4 v = *(const float4*)(src + (size_t)l*R*Cc + (size_t)r*Cc + c4*4);
    ushort4 hi, lo; split4(v, hi, lo);
    *(ushort4*)(dh + (size_t)l*R*outC + (size_t)r*outC + colOff + c4*4) = hi;
    *(ushort4*)(dl + (size_t)l*R*outC + (size_t)r*outC + colOff + c4*4) = lo;
}

__global__ void concat_bias(const float* __restrict__ bq, const float* __restrict__ bk,
                            const float* __restrict__ bv, float* __restrict__ dst)
{
    int id = blockIdx.x*256 + threadIdx.x;
    if (id >= LL*HH) return;
    int l = id / HH, c = id % HH;
    dst[(size_t)l*H3 + c]        = bq[id];
    dst[(size_t)l*H3 + HH + c]   = bk[id];
    dst[(size_t)l*H3 + 2*HH + c] = bv[id];
}

__global__ void split_x(const float* __restrict__ src,
                        __nv_bfloat16* __restrict__ dh,
                        __nv_bfloat16* __restrict__ dl, int n4)
{
    int id = blockIdx.x*256 + threadIdx.x;
    if (id >= n4) return;
    float4 v = *(const float4*)(src + (size_t)id*4);
    ushort4 hi, lo; split4(v, hi, lo);
    *(ushort4*)(dh + (size_t)id*4) = hi;
    *(ushort4*)(dl + (size_t)id*4) = lo;
}

// ---------------------------------------------------------------------------
// bf16x3 GEMM v2: block 64x128x16, warp tile 32x32, 4-stage cp.async,
// 3 CTAs/SM (6 warps/SMSP: bubble coverage for the tensor pipe).
// SPLITK: gridDim.z=2; z=0 -> EPI into Cf, z=1 -> raw partial into Cf2.
// EPI: 0 = bias -> split out; 1 = bias + residual -> fp32; 2 = bias+GELU -> split
// ---------------------------------------------------------------------------
#define LAS   24            // A row stride (shorts): 16 + 8 pad
#define LBS   136           // B row stride (shorts): 128 + 8 pad
#define ASZ   (64*LAS)      // 1536 shorts
#define BSZ   (16*LBS)      // 2176 shorts
#define STG   (2*ASZ + 2*BSZ)          // 7424 shorts = 14848 B
#define GEMM_SMEM (4*STG*2)            // 59392 B

template<int EPI, int SPLITK>
__global__ void __launch_bounds__(256, 3)
gemm_cp(const __nv_bfloat16* __restrict__ AH, const __nv_bfloat16* __restrict__ AL, int lda,
        const __nv_bfloat16* __restrict__ BH, const __nv_bfloat16* __restrict__ BL, int ldb,
        const float* __restrict__ bias,
        const __nv_bfloat16* __restrict__ RH, const __nv_bfloat16* __restrict__ RL, int ldr,
        float* __restrict__ Cf, float* __restrict__ Cf2,
        __nv_bfloat16* __restrict__ CH, __nv_bfloat16* __restrict__ CL,
        int ldc, int K)
{
    extern __shared__ __align__(16) unsigned short sm[];
    const uint32_t smb = smem_u32(sm);

    const int tid = threadIdx.x, lane = tid & 31, wid = tid >> 5;
    const int wm = wid >> 2, wn = wid & 3;          // 2x4 warp grid, tile 32x32
    const int m0 = blockIdx.y * 64, n0 = blockIdx.x * 128;

    if (SPLITK) {
        const size_t koff = (size_t)blockIdx.z * K;
        AH += koff; AL += koff;
        BH += koff * ldb; BL += koff * ldb;
    }

    float acc[2][4][4] = {};

    auto issue = [&](int st, int k0) {
        const uint32_t base = smb + st*STG*2;
        // B: 16 rows x 16 chunks = 256 -> 1/thread (hi + lo)
        {
            int r = tid >> 4, cc = tid & 15;
            uint32_t d = base + 2*ASZ*2 + (uint32_t)(r*LBS + cc*8)*2;
            const size_t off = (size_t)(k0+r)*ldb + n0 + cc*8;
            CP_ASYNC16(d,         BH + off);
            CP_ASYNC16(d + BSZ*2, BL + off);
        }
        // A: 64 rows x 2 chunks = 128 per matrix; tid<128 -> hi, tid>=128 -> lo
        {
            int ar = (tid & 127) >> 1, ac = tid & 1;
            const __nv_bfloat16* Asrc = (tid < 128) ? AH : AL;
            uint32_t d = base + ((tid < 128) ? 0u : (uint32_t)ASZ*2)
                       + (uint32_t)(ar*LAS + ac*8)*2;
            CP_ASYNC16(d, Asrc + (size_t)(m0+ar)*lda + k0 + ac*8);
        }
    };

    const int nk = K / 16;
    issue(0, 0);  CP_COMMIT();
    issue(1, 16); CP_COMMIT();
    issue(2, 32); CP_COMMIT();

    for (int kt = 0; kt < nk; ++kt) {
        CP_WAIT2();
        __syncthreads();
        if (kt + 3 < nk) issue((kt+3) & 3, (kt+3)*16);
        CP_COMMIT();

        const unsigned short* Ah = sm + (kt & 3)*STG;
        const unsigned short* Al = Ah + ASZ;
        const unsigned short* Bh = Al + ASZ;
        const unsigned short* Bl = Bh + BSZ;

        uint32_t ah[2][4], al[2][4];
        #pragma unroll
        for (int mt = 0; mt < 2; ++mt) {
            int r = wm*32 + mt*16 + (lane & 15);
            int c = (lane >> 4) << 3;
            ldsm_x4(ah[mt], smem_u32(Ah + r*LAS + c));
            ldsm_x4(al[mt], smem_u32(Al + r*LAS + c));
        }
        #pragma unroll
        for (int np = 0; np < 2; ++np) {
            uint32_t bh[4], bl[4];
            int off = (lane & 15)*LBS + wn*32 + np*16 + ((lane >> 4) << 3);
            ldsm_x4t(bh, smem_u32(Bh + off));
            ldsm_x4t(bl, smem_u32(Bl + off));
            #pragma unroll
            for (int s = 0; s < 2; ++s)
                #pragma unroll
                for (int mt = 0; mt < 2; ++mt)
                    mma16816(acc[mt][np*2+s], ah[mt], bh + s*2);
            #pragma unroll
            for (int s = 0; s < 2; ++s)
                #pragma unroll
                for (int mt = 0; mt < 2; ++mt)
                    mma16816(acc[mt][np*2+s], al[mt], bh + s*2);
            #pragma unroll
            for (int s = 0; s < 2; ++s)
                #pragma unroll
                for (int mt = 0; mt < 2; ++mt)
                    mma16816(acc[mt][np*2+s], ah[mt], bl + s*2);
        }
    }

    // --- epilogue ---
    const bool plain = SPLITK && (blockIdx.z == 1);
    #pragma unroll
    for (int mt = 0; mt < 2; ++mt) {
        #pragma unroll
        for (int nt = 0; nt < 4; ++nt) {
            const int row = m0 + wm*32 + mt*16 + (lane >> 2);
            const int col = n0 + wn*32 + nt*8 + (lane & 3)*2;
            #pragma unroll
            for (int h = 0; h < 2; ++h) {
                const int r2 = row + h*8;
                float v0 = acc[mt][nt][h*2+0];
                float v1 = acc[mt][nt][h*2+1];
                if (plain) {
                    *(float2*)(Cf2 + (size_t)r2*ldc + col) = make_float2(v0, v1);
                    continue;
                }
                v0 += bias[col]; v1 += bias[col+1];
                if (EPI == 1) {
                    const size_t ri = (size_t)r2*ldr + col;
                    const ushort2 rh = *(const ushort2*)(RH + ri);
                    const ushort2 rl = *(const ushort2*)(RL + ri);
                    v0 += bf2f(rh.x) + bf2f(rl.x);
                    v1 += bf2f(rh.y) + bf2f(rl.y);
                    *(float2*)(Cf + (size_t)r2*ldc + col) = make_float2(v0, v1);
                } else {
                    if (EPI == 2) {
                        v0 = 0.5f*v0*(1.0f + erff(v0 * 0.70710678118654752f));
                        v1 = 0.5f*v1*(1.0f + erff(v1 * 0.70710678118654752f));
                    }
                    unsigned short h0, l0, h1, l1;
                    split1(v0, h0, l0); split1(v1, h1, l1);
                    const size_t ci = (size_t)r2*ldc + col;
                    *(ushort2*)(CH + ci) = make_ushort2(h0, h1);
                    *(ushort2*)(CL + ci) = make_ushort2(l0, l1);
                }
            }
        }
    }
}

// ---------------------------------------------------------------------------
// Fused flash attention v2: 64-row KV tiles -> 74 KB smem -> 2 CTAs/SM.
// Q fragments re-loaded from smem per j-iter (register budget for occ=2).
// ---------------------------------------------------------------------------
#define DPF 72
#define FLASH_SMEM ((2*128*DPF + 4*64*DPF) * 2)   // 73728 B

__global__ void __launch_bounds__(256, 2)
flash_attn(const __nv_bfloat16* __restrict__ QKVH,
           const __nv_bfloat16* __restrict__ QKVL,
           __nv_bfloat16* __restrict__ OH, __nv_bfloat16* __restrict__ OL)
{
    extern __shared__ __align__(16) unsigned short dynsm[];
    unsigned short* Qh = dynsm;
    unsigned short* Ql = Qh + 128*DPF;
    unsigned short* Kh = Ql + 128*DPF;
    unsigned short* Kl = Kh + 64*DPF;
    unsigned short* Vh = Kl + 64*DPF;
    unsigned short* Vl = Vh + 64*DPF;

    const int tid = threadIdx.x, lane = tid & 31, w = tid >> 5;
    const int b = blockIdx.y / NHH, hh = blockIdx.y % NHH;
    const int q0 = blockIdx.x * 128;
    const size_t qoff = ((size_t)b*SS + q0)*H3 + hh*DHH;
    const size_t koff = (size_t)b*SS*H3 + HH + hh*DHH;
    const size_t voff = (size_t)b*SS*H3 + 2*HH + hh*DHH;

    #pragma unroll
    for (int it = 0; it < 4; ++it) {
        int id = tid + it*256;
        int r = id >> 3, c8 = id & 7;
        *(uint4*)&Qh[r*DPF + c8*8] = *(const uint4*)(QKVH + qoff + (size_t)r*H3 + c8*8);
        *(uint4*)&Ql[r*DPF + c8*8] = *(const uint4*)(QKVL + qoff + (size_t)r*H3 + c8*8);
    }
    __syncthreads();

    float oacc[8][4] = {};
    float mrow[2] = {-1e30f, -1e30f};
    float lrow[2] = {0.0f, 0.0f};

    const int kb_row = (lane & 7) + ((lane & 16) >> 1);
    const int kb_col = ((lane >> 3) & 1) * 8;

    for (int j = 0; j < 8; ++j) {
        const size_t s0 = (size_t)j*64;
        #pragma unroll
        for (int it = 0; it < 2; ++it) {
            int id = tid + it*256;
            int r = id >> 3, c8 = id & 7;
            const size_t gk = koff + (s0+r)*H3 + c8*8;
            const size_t gv = voff + (s0+r)*H3 + c8*8;
            *(uint4*)&Kh[r*DPF + c8*8] = *(const uint4*)(QKVH + gk);
            *(uint4*)&Kl[r*DPF + c8*8] = *(const uint4*)(QKVL + gk);
            *(uint4*)&Vh[r*DPF + c8*8] = *(const uint4*)(QKVH + gv);
            *(uint4*)&Vl[r*DPF + c8*8] = *(const uint4*)(QKVL + gv);
        }
        __syncthreads();

        // --- S = Q K^T : warp tile 16x64 over this 64-row KV chunk ---
        float sacc[8][4] = {};
        #pragma unroll
        for (int ks = 0; ks < 4; ++ks) {
            uint32_t qh[4], ql[4];
            int qr = w*16 + (lane & 15);
            int qc = ks*16 + ((lane >> 4) << 3);
            ldsm_x4(qh, smem_u32(Qh + qr*DPF + qc));
            ldsm_x4(ql, smem_u32(Ql + qr*DPF + qc));
            #pragma unroll
            for (int np = 0; np < 4; ++np) {
                uint32_t bh[4], bl[4];
                int off = (np*16 + kb_row)*DPF + ks*16 + kb_col;
                ldsm_x4(bh, smem_u32(Kh + off));
                ldsm_x4(bl, smem_u32(Kl + off));
                #pragma unroll
                for (int s = 0; s < 2; ++s) mma16816(sacc[np*2+s], qh, bh + s*2);
                #pragma unroll
                for (int s = 0; s < 2; ++s) mma16816(sacc[np*2+s], ql, bh + s*2);
                #pragma unroll
                for (int s = 0; s < 2; ++s) mma16816(sacc[np*2+s], qh, bl + s*2);
            }
        }
        #pragma unroll
        for (int nt = 0; nt < 8; ++nt) {
            sacc[nt][0] *= 0.125f; sacc[nt][1] *= 0.125f;
            sacc[nt][2] *= 0.125f; sacc[nt][3] *= 0.125f;
        }

        // --- online softmax ---
        #pragma unroll
        for (int h = 0; h < 2; ++h) {
            float mx = -1e30f;
            #pragma unroll
            for (int nt = 0; nt < 8; ++nt)
                mx = fmaxf(mx, fmaxf(sacc[nt][2*h], sacc[nt][2*h+1]));
            mx = fmaxf(mx, __shfl_xor_sync(0xffffffffu, mx, 1));
            mx = fmaxf(mx, __shfl_xor_sync(0xffffffffu, mx, 2));
            float mnew = fmaxf(mrow[h], mx);
            float corr = expf(mrow[h] - mnew);
            mrow[h] = mnew;
            float sum = 0.0f;
            #pragma unroll
            for (int nt = 0; nt < 8; ++nt) {
                float p0 = expf(sacc[nt][2*h]   - mnew);
                float p1 = expf(sacc[nt][2*h+1] - mnew);
                sacc[nt][2*h] = p0; sacc[nt][2*h+1] = p1;
                sum += p0 + p1;
            }
            sum += __shfl_xor_sync(0xffffffffu, sum, 1);
            sum += __shfl_xor_sync(0xffffffffu, sum, 2);
            lrow[h] = lrow[h]*corr + sum;
            #pragma unroll
            for (int nt = 0; nt < 8; ++nt) {
                oacc[nt][2*h]   *= corr;
                oacc[nt][2*h+1] *= corr;
            }
        }

        // --- O += P V ---
        #pragma unroll
        for (int ks = 0; ks < 4; ++ks) {
            uint32_t ph[4], pl[4];
            #pragma unroll
            for (int q = 0; q < 2; ++q) {
                #pragma unroll
                for (int hf = 0; hf < 2; ++hf) {
                    float x = sacc[2*ks+q][2*hf];
                    float y = sacc[2*ks+q][2*hf+1];
                    unsigned short hx, lx, hy, ly;
                    split1(x, hx, lx); split1(y, hy, ly);
                    ph[2*q+hf] = (uint32_t)hx | ((uint32_t)hy << 16);
                    pl[2*q+hf] = (uint32_t)lx | ((uint32_t)ly << 16);
                }
            }
            #pragma unroll
            for (int np = 0; np < 4; ++np) {
                uint32_t bh[4], bl[4];
                int off = (ks*16 + (lane & 15))*DPF + np*16 + ((lane >> 4) << 3);
                ldsm_x4t(bh, smem_u32(Vh + off));
                ldsm_x4t(bl, smem_u32(Vl + off));
                #pragma unroll
                for (int s = 0; s < 2; ++s) mma16816(oacc[np*2+s], ph, bh + s*2);
                #pragma unroll
                for (int s = 0; s < 2; ++s) mma16816(oacc[np*2+s], pl, bh + s*2);
                #pragma unroll
                for (int s = 0; s < 2; ++s) mma16816(oacc[np*2+s], ph, bl + s*2);
            }
        }
        __syncthreads();
    }

    const size_t obase = (size_t)b*SS*HH + (size_t)hh*DHH;
    const int orow = w*16 + (lane >> 2);
    #pragma unroll
    for (int h = 0; h < 2; ++h) {
        const float inv = 1.0f / lrow[h];
        const int r = q0 + orow + h*8;
        #pragma unroll
        for (int nt = 0; nt < 8; ++nt) {
            const int c = nt*8 + (lane & 3)*2;
            unsigned short h0, l0, h1, l1;
            split1(oacc[nt][2*h]*inv,   h0, l0);
            split1(oacc[nt][2*h+1]*inv, h1, l1);
            const size_t oi = obase + (size_t)r*HH + c;
            *(ushort2*)(OH + oi) = make_ushort2(h0, h1);
            *(ushort2*)(OL + oi) = make_ushort2(l0, l1);
        }
    }
}

// ---------------------------------------------------------------------------
// LayerNorm (warp per row). Sums X + X2 (split-K merge).
// SPLIT=1 -> bf16 hi/lo out; SPLIT=0 -> fp32 out.
// ---------------------------------------------------------------------------
template<int SPLIT>
__global__ void layernorm768(const float* __restrict__ X,
                             const float* __restrict__ X2,
                             const float* __restrict__ g,
                             const float* __restrict__ b,
                             float* __restrict__ Yf,
                             __nv_bfloat16* __restrict__ YH,
                             __nv_bfloat16* __restrict__ YL, int rows)
{
    const int warp = (blockIdx.x * blockDim.x + threadIdx.x) >> 5;
    const int lane = threadIdx.x & 31;
    if (warp >= rows) return;
    const float4* x  = (const float4*)(X  + (size_t)warp * 768);
    const float4* x2 = (const float4*)(X2 + (size_t)warp * 768);

    float4 v[6];
    float s = 0.0f;
    #pragma unroll
    for (int i = 0; i < 6; ++i) {
        float4 a = x[lane + i*32];
        float4 c = x2[lane + i*32];
        v[i] = make_float4(a.x + c.x, a.y + c.y, a.z + c.z, a.w + c.w);
        s += v[i].x + v[i].y + v[i].z + v[i].w;
    }
    #pragma unroll
    for (int o = 16; o; o >>= 1) s += __shfl_xor_sync(0xffffffffu, s, o);
    const float mean = s * (1.0f / 768.0f);

    float var = 0.0f;
    #pragma unroll
    for (int i = 0; i < 6; ++i) {
        float dx = v[i].x - mean, dy = v[i].y - mean, dz = v[i].z - mean, dw = v[i].w - mean;
        var += dx*dx + dy*dy + dz*dz + dw*dw;
    }
    #pragma unroll
    for (int o = 16; o; o >>= 1) var += __shfl_xor_sync(0xffffffffu, var, o);
    const float rs = rsqrtf(var * (1.0f / 768.0f) + 1e-12f);

    const float4* gg = (const float4*)g;
    const float4* bb = (const float4*)b;
    #pragma unroll
    for (int i = 0; i < 6; ++i) {
        const int c = lane + i*32;
        const float4 gv = gg[c], bv = bb[c];
        float4 o4;
        o4.x = (v[i].x - mean) * rs * gv.x + bv.x;
        o4.y = (v[i].y - mean) * rs * gv.y + bv.y;
        o4.z = (v[i].z - mean) * rs * gv.z + bv.z;
        o4.w = (v[i].w - mean) * rs * gv.w + bv.w;
        if (SPLIT) {
            ushort4 hi, lo; split4(o4, hi, lo);
            *(ushort4*)(YH + (size_t)warp*768 + c*4) = hi;
            *(ushort4*)(YL + (size_t)warp*768 + c*4) = lo;
        } else {
            *(float4*)(Yf + (size_t)warp*768 + c*4) = o4;
        }
    }
}

// ---------------------------------------------------------------------------
// Launch
// ---------------------------------------------------------------------------
extern "C" void kernel_launch(void* const* d_in, const int* in_sizes, int n_in,
                              void* d_out, int out_size)
{
    (void)in_sizes; (void)n_in; (void)out_size;
    const float* hs  = (const float*)d_in[0];
    const float* Wq  = (const float*)d_in[1];  const float* bq  = (const float*)d_in[2];
    const float* Wk  = (const float*)d_in[3];  const float* bk  = (const float*)d_in[4];
    const float* Wv  = (const float*)d_in[5];  const float* bv  = (const float*)d_in[6];
    const float* Wo  = (const float*)d_in[7];  const float* bo  = (const float*)d_in[8];
    const float* g1  = (const float*)d_in[9];  const float* b1  = (const float*)d_in[10];
    const float* Wi  = (const float*)d_in[11]; const float* bi  = (const float*)d_in[12];
    const float* Wo2 = (const float*)d_in[13]; const float* bo2 = (const float*)d_in[14];
    const float* g2  = (const float*)d_in[15]; const float* b2  = (const float*)d_in[16];

    __nv_bfloat16 *XH, *XL, *QKVH, *QKVL, *CH, *CL, *AH, *AL, *IH, *IL;
    __nv_bfloat16 *WqkvH, *WqkvL, *WoH, *WoL, *WiH, *WiL, *Wo2H, *Wo2L;
    float *T, *T2, *bqkv;
    cudaGetSymbolAddress((void**)&XH, g_XH);   cudaGetSymbolAddress((void**)&XL, g_XL);
    cudaGetSymbolAddress((void**)&QKVH, g_QKVH); cudaGetSymbolAddress((void**)&QKVL, g_QKVL);
    cudaGetSymbolAddress((void**)&CH, g_CH);   cudaGetSymbolAddress((void**)&CL, g_CL);
    cudaGetSymbolAddress((void**)&AH, g_AH);   cudaGetSymbolAddress((void**)&AL, g_AL);
    cudaGetSymbolAddress((void**)&IH, g_IH);   cudaGetSymbolAddress((void**)&IL, g_IL);
    cudaGetSymbolAddress((void**)&T,  g_T);    cudaGetSymbolAddress((void**)&T2, g_T2);
    cudaGetSymbolAddress((void**)&bqkv, g_bqkv);
    cudaGetSymbolAddress((void**)&WqkvH, g_WqkvH); cudaGetSymbolAddress((void**)&WqkvL, g_WqkvL);
    cudaGetSymbolAddress((void**)&WoH, g_WoH); cudaGetSymbolAddress((void**)&WoL, g_WoL);
    cudaGetSymbolAddress((void**)&WiH, g_WiH); cudaGetSymbolAddress((void**)&WiL, g_WiL);
    cudaGetSymbolAddress((void**)&Wo2H, g_Wo2H); cudaGetSymbolAddress((void**)&Wo2L, g_Wo2L);

    cudaFuncSetAttribute((const void*)gemm_cp<0,0>, cudaFuncAttributeMaxDynamicSharedMemorySize, GEMM_SMEM);
    cudaFuncSetAttribute((const void*)gemm_cp<1,1>, cudaFuncAttributeMaxDynamicSharedMemorySize, GEMM_SMEM);
    cudaFuncSetAttribute((const void*)gemm_cp<2,0>, cudaFuncAttributeMaxDynamicSharedMemorySize, GEMM_SMEM);
    cudaFuncSetAttribute((const void*)flash_attn, cudaFuncAttributeMaxDynamicSharedMemorySize, FLASH_SMEM);

    // --- preprocessing ---
    split_all<<<dim3(HH*II/1024, LL, 6), 256>>>(Wq, Wk, Wv, Wo, Wi, Wo2,
        WqkvH, WqkvL, WoH, WoL, WiH, WiL, Wo2H, Wo2L);
    concat_bias<<<(LL*HH + 255)/256, 256>>>(bq, bk, bv, bqkv);
    split_x<<<(M0*HH/4 + 255)/256, 256>>>(hs, XH, XL, M0*HH/4);

    for (int l = 0; l < LL; ++l) {
        const __nv_bfloat16* wqkvH = WqkvH + (size_t)l*HH*H3;
        const __nv_bfloat16* wqkvL = WqkvL + (size_t)l*HH*H3;
        const __nv_bfloat16* woH   = WoH   + (size_t)l*HH*HH;
        const __nv_bfloat16* woL   = WoL   + (size_t)l*HH*HH;
        const __nv_bfloat16* wiH   = WiH   + (size_t)l*HH*II;
        const __nv_bfloat16* wiL   = WiL   + (size_t)l*HH*II;
        const __nv_bfloat16* wo2H  = Wo2H  + (size_t)l*II*HH;
        const __nv_bfloat16* wo2L  = Wo2L  + (size_t)l*II*HH;
        const float* bqkvl = bqkv + (size_t)l*H3;
        const float* bol   = bo   + (size_t)l*HH;
        const float* bil   = bi   + (size_t)l*II;
        const float* bo2l  = bo2  + (size_t)l*HH;

        // QKV projection (2304 CTAs of 64x128)
        gemm_cp<0,0><<<dim3(H3/128, M0/64), 256, GEMM_SMEM>>>(
            XH, XL, HH, wqkvH, wqkvL, H3, bqkvl,
            nullptr, nullptr, 0, nullptr, nullptr, QKVH, QKVL, H3, HH);

        // fused attention -> ctx (hi/lo)
        flash_attn<<<dim3(SS/128, NBA), 256, FLASH_SMEM>>>(QKVH, QKVL, CH, CL);

        // O projection + residual(X): split-K=2 (1536 CTAs of K=384)
        gemm_cp<1,1><<<dim3(HH/128, M0/64, 2), 256, GEMM_SMEM>>>(
            CH, CL, HH, woH, woL, HH, bol,
            XH, XL, HH, T, T2, nullptr, nullptr, HH, HH/2);
        layernorm768<1><<<M0/8, 256>>>(T, T2, g1 + (size_t)l*HH, b1 + (size_t)l*HH,
                                       nullptr, AH, AL, M0);

        // FFN1: I = gelu(A @ Wi + bi)  (3072 CTAs)
        gemm_cp<2,0><<<dim3(II/128, M0/64), 256, GEMM_SMEM>>>(
            AH, AL, HH, wiH, wiL, II, bil,
            nullptr, nullptr, 0, nullptr, nullptr, IH, IL, II, HH);

        // FFN2 + residual(A): split-K=2 (1536 CTAs of K=1536)
        gemm_cp<1,1><<<dim3(HH/128, M0/64, 2), 256, GEMM_SMEM>>>(
            IH, IL, II, wo2H, wo2L, HH, bo2l,
            AH, AL, HH, T, T2, nullptr, nullptr, HH, II/2);

        if (l == LL-1) {
            layernorm768<0><<<M0/8, 256>>>(T, T2, g2 + (size_t)l*HH, b2 + (size_t)l*HH,
                                           (float*)d_out, nullptr, nullptr, M0);
        } else {
            layernorm768<1><<<M0/8, 256>>>(T, T2, g2 + (size_t)l*HH, b2 + (size_t)l*HH,
                                           nullptr, XH, XL, M0);
        }
    }
}

// round 15
// speedup vs baseline: 1.5129x; 1.4051x over previous
#include <cuda_runtime.h>
#include <cuda_fp16.h>
#include <math.h>
#include <stdint.h>

// Problem constants
#define BB   16
#define SS   512
#define HH   768
#define II   3072
#define NHH  12
#define DHH  64
#define LL   6
#define M0   (BB*SS)       // 8192 tokens
#define NBA  (BB*NHH)      // 192 attention batches
#define H3   (3*HH)        // 2304

// ---------------------------------------------------------------------------
// Scratch buffers. Activations: fp16 hi/lo pairs (hi+lo ~ 22-bit mantissa).
// Weights: fp16 hi ONLY (2-term scheme: A_full x W_fp16).
// ---------------------------------------------------------------------------
__device__ __half g_XH[M0*HH],   g_XL[M0*HH];
__device__ __half g_QKVH[M0*H3], g_QKVL[M0*H3];
__device__ __half g_CH[M0*HH],   g_CL[M0*HH];
__device__ __half g_AH[M0*HH],   g_AL[M0*HH];
__device__ __half g_IH[M0*II],   g_IL[M0*II];
__device__ float g_T[M0*HH];
__device__ float g_T2[M0*HH];
__device__ __half g_Wqkv[LL*HH*H3];
__device__ __half g_Wo[LL*HH*HH];
__device__ __half g_Wi[LL*HH*II];
__device__ __half g_Wo2[LL*II*HH];
__device__ float g_bqkv[LL*H3];

// ---------------------------------------------------------------------------
// PTX helpers
// ---------------------------------------------------------------------------
__device__ __forceinline__ uint32_t smem_u32(const void* p) {
    return (uint32_t)__cvta_generic_to_shared(p);
}
__device__ __forceinline__ void ldsm_x4(uint32_t* r, uint32_t a) {
    asm volatile("ldmatrix.sync.aligned.m8n8.x4.shared.b16 {%0,%1,%2,%3}, [%4];"
        : "=r"(r[0]), "=r"(r[1]), "=r"(r[2]), "=r"(r[3]) : "r"(a));
}
__device__ __forceinline__ void ldsm_x4t(uint32_t* r, uint32_t a) {
    asm volatile("ldmatrix.sync.aligned.m8n8.x4.trans.shared.b16 {%0,%1,%2,%3}, [%4];"
        : "=r"(r[0]), "=r"(r[1]), "=r"(r[2]), "=r"(r[3]) : "r"(a));
}
__device__ __forceinline__ void mma16816(float* c, const uint32_t* a, const uint32_t* b) {
    asm volatile(
        "mma.sync.aligned.m16n8k16.row.col.f32.f16.f16.f32 "
        "{%0,%1,%2,%3}, {%4,%5,%6,%7}, {%8,%9}, {%0,%1,%2,%3};"
        : "+f"(c[0]), "+f"(c[1]), "+f"(c[2]), "+f"(c[3])
        : "r"(a[0]), "r"(a[1]), "r"(a[2]), "r"(a[3]), "r"(b[0]), "r"(b[1]));
}
#define CP_ASYNC16(dst, src) \
    asm volatile("cp.async.cg.shared.global [%0], [%1], 16;" :: "r"(dst), "l"(src) : "memory")
#define CP_COMMIT() asm volatile("cp.async.commit_group;" ::: "memory")
#define CP_WAIT2()  asm volatile("cp.async.wait_group 2;" ::: "memory")

// fp32 -> (fp16 hi, fp16 lo) residual split (hi+lo carries ~22 mantissa bits)
__device__ __forceinline__ void split1(float x, unsigned short& hi, unsigned short& lo) {
    __half h = __float2half(x);
    hi = __half_as_ushort(h);
    float r = x - __half2float(h);
    lo = __half_as_ushort(__float2half(r));
}
__device__ __forceinline__ void split4(float4 v, ushort4& hi, ushort4& lo) {
    split1(v.x, hi.x, lo.x);
    split1(v.y, hi.y, lo.y);
    split1(v.z, hi.z, lo.z);
    split1(v.w, hi.w, lo.w);
}
__device__ __forceinline__ float h2f(unsigned short u) {
    return __half2float(__ushort_as_half(u));
}

// ---------------------------------------------------------------------------
// Preprocessing: weights -> fp16 (round-to-nearest, hi only)
// ---------------------------------------------------------------------------
__global__ void split_all(const float* __restrict__ Wq, const float* __restrict__ Wk,
                          const float* __restrict__ Wv, const float* __restrict__ Wo,
                          const float* __restrict__ Wi, const float* __restrict__ Wo2,
                          __half* __restrict__ Wqkv, __half* __restrict__ WoD,
                          __half* __restrict__ WiD,  __half* __restrict__ Wo2D)
{
    const int l = blockIdx.y;
    const float* src; __half* dh;
    int R, Cc, outC, colOff;
    switch (blockIdx.z) {
        case 0: src = Wq;  dh = Wqkv; R = HH; Cc = HH; outC = H3; colOff = 0;    break;
        case 1: src = Wk;  dh = Wqkv; R = HH; Cc = HH; outC = H3; colOff = HH;   break;
        case 2: src = Wv;  dh = Wqkv; R = HH; Cc = HH; outC = H3; colOff = 2*HH; break;
        case 3: src = Wo;  dh = WoD;  R = HH; Cc = HH; outC = HH; colOff = 0;    break;
        case 4: src = Wi;  dh = WiD;  R = HH; Cc = II; outC = II; colOff = 0;    break;
        default:src = Wo2; dh = Wo2D; R = II; Cc = HH; outC = HH; colOff = 0;    break;
    }
    int id = blockIdx.x*256 + threadIdx.x;
    if (id >= R*Cc/4) return;
    int r = id / (Cc/4), c4 = id % (Cc/4);
    float4 v = *(const float4*)(src + (size_t)l*R*Cc + (size_t)r*Cc + c4*4);
    ushort4 hi;
    hi.x = __half_as_ushort(__float2half(v.x));
    hi.y = __half_as_ushort(__float2half(v.y));
    hi.z = __half_as_ushort(__float2half(v.z));
    hi.w = __half_as_ushort(__float2half(v.w));
    *(ushort4*)(dh + (size_t)l*R*outC + (size_t)r*outC + colOff + c4*4) = hi;
}

__global__ void concat_bias(const float* __restrict__ bq, const float* __restrict__ bk,
                            const float* __restrict__ bv, float* __restrict__ dst)
{
    int id = blockIdx.x*256 + threadIdx.x;
    if (id >= LL*HH) return;
    int l = id / HH, c = id % HH;
    dst[(size_t)l*H3 + c]        = bq[id];
    dst[(size_t)l*H3 + HH + c]   = bk[id];
    dst[(size_t)l*H3 + 2*HH + c] = bv[id];
}

__global__ void split_x(const float* __restrict__ src,
                        __half* __restrict__ dh, __half* __restrict__ dl, int n4)
{
    int id = blockIdx.x*256 + threadIdx.x;
    if (id >= n4) return;
    float4 v = *(const float4*)(src + (size_t)id*4);
    ushort4 hi, lo; split4(v, hi, lo);
    *(ushort4*)(dh + (size_t)id*4) = hi;
    *(ushort4*)(dl + (size_t)id*4) = lo;
}

// ---------------------------------------------------------------------------
// fp16x2 GEMM: C = (AH+AL) @ B_fp16. Block 64x128x16, warp tile 32x32,
// 4-stage cp.async, 3 CTAs/SM. 2 MMA terms per tile (was 3).
// SPLITK: gridDim.z=2; z=0 -> EPI into Cf, z=1 -> raw partial into Cf2.
// EPI: 0 = bias -> split out; 1 = bias + residual -> fp32; 2 = bias+GELU -> split
// ---------------------------------------------------------------------------
#define LAS   24            // A row stride (shorts): 16 + 8 pad
#define LBS   136           // B row stride (shorts): 128 + 8 pad
#define ASZ   (64*LAS)      // 1536 shorts
#define BSZ   (16*LBS)      // 2176 shorts
#define STG   (2*ASZ + BSZ)            // 5248 shorts = 10496 B
#define GEMM_SMEM (4*STG*2)            // 41984 B

template<int EPI, int SPLITK>
__global__ void __launch_bounds__(256, 3)
gemm_cp(const __half* __restrict__ AH, const __half* __restrict__ AL, int lda,
        const __half* __restrict__ B, int ldb,
        const float* __restrict__ bias,
        const __half* __restrict__ RH, const __half* __restrict__ RL, int ldr,
        float* __restrict__ Cf, float* __restrict__ Cf2,
        __half* __restrict__ CH, __half* __restrict__ CL,
        int ldc, int K)
{
    extern __shared__ __align__(16) unsigned short sm[];
    const uint32_t smb = smem_u32(sm);

    const int tid = threadIdx.x, lane = tid & 31, wid = tid >> 5;
    const int wm = wid >> 2, wn = wid & 3;          // 2x4 warp grid, tile 32x32
    const int m0 = blockIdx.y * 64, n0 = blockIdx.x * 128;

    if (SPLITK) {
        const size_t koff = (size_t)blockIdx.z * K;
        AH += koff; AL += koff;
        B  += koff * ldb;
    }

    float acc[2][4][4] = {};

    auto issue = [&](int st, int k0) {
        const uint32_t base = smb + st*STG*2;
        // B: 16 rows x 16 chunks = 256 -> 1 cp.async/thread
        {
            int r = tid >> 4, cc = tid & 15;
            uint32_t d = base + 2*ASZ*2 + (uint32_t)(r*LBS + cc*8)*2;
            CP_ASYNC16(d, B + (size_t)(k0+r)*ldb + n0 + cc*8);
        }
        // A: 64 rows x 2 chunks = 128 per matrix; tid<128 -> hi, tid>=128 -> lo
        {
            int ar = (tid & 127) >> 1, ac = tid & 1;
            const __half* Asrc = (tid < 128) ? AH : AL;
            uint32_t d = base + ((tid < 128) ? 0u : (uint32_t)ASZ*2)
                       + (uint32_t)(ar*LAS + ac*8)*2;
            CP_ASYNC16(d, Asrc + (size_t)(m0+ar)*lda + k0 + ac*8);
        }
    };

    const int nk = K / 16;
    issue(0, 0);  CP_COMMIT();
    issue(1, 16); CP_COMMIT();
    issue(2, 32); CP_COMMIT();

    for (int kt = 0; kt < nk; ++kt) {
        CP_WAIT2();
        __syncthreads();
        if (kt + 3 < nk) issue((kt+3) & 3, (kt+3)*16);
        CP_COMMIT();

        const unsigned short* Ah = sm + (kt & 3)*STG;
        const unsigned short* Al = Ah + ASZ;
        const unsigned short* Bh = Al + ASZ;

        uint32_t ah[2][4], al[2][4];
        #pragma unroll
        for (int mt = 0; mt < 2; ++mt) {
            int r = wm*32 + mt*16 + (lane & 15);
            int c = (lane >> 4) << 3;
            ldsm_x4(ah[mt], smem_u32(Ah + r*LAS + c));
            ldsm_x4(al[mt], smem_u32(Al + r*LAS + c));
        }
        #pragma unroll
        for (int np = 0; np < 2; ++np) {
            uint32_t bh[4];
            int off = (lane & 15)*LBS + wn*32 + np*16 + ((lane >> 4) << 3);
            ldsm_x4t(bh, smem_u32(Bh + off));
            #pragma unroll
            for (int s = 0; s < 2; ++s)
                #pragma unroll
                for (int mt = 0; mt < 2; ++mt)
                    mma16816(acc[mt][np*2+s], ah[mt], bh + s*2);
            #pragma unroll
            for (int s = 0; s < 2; ++s)
                #pragma unroll
                for (int mt = 0; mt < 2; ++mt)
                    mma16816(acc[mt][np*2+s], al[mt], bh + s*2);
        }
    }

    // --- epilogue ---
    const bool plain = SPLITK && (blockIdx.z == 1);
    #pragma unroll
    for (int mt = 0; mt < 2; ++mt) {
        #pragma unroll
        for (int nt = 0; nt < 4; ++nt) {
            const int row = m0 + wm*32 + mt*16 + (lane >> 2);
            const int col = n0 + wn*32 + nt*8 + (lane & 3)*2;
            #pragma unroll
            for (int h = 0; h < 2; ++h) {
                const int r2 = row + h*8;
                float v0 = acc[mt][nt][h*2+0];
                float v1 = acc[mt][nt][h*2+1];
                if (plain) {
                    *(float2*)(Cf2 + (size_t)r2*ldc + col) = make_float2(v0, v1);
                    continue;
                }
                v0 += bias[col]; v1 += bias[col+1];
                if (EPI == 1) {
                    const size_t ri = (size_t)r2*ldr + col;
                    const ushort2 rh = *(const ushort2*)(RH + ri);
                    const ushort2 rl = *(const ushort2*)(RL + ri);
                    v0 += h2f(rh.x) + h2f(rl.x);
                    v1 += h2f(rh.y) + h2f(rl.y);
                    *(float2*)(Cf + (size_t)r2*ldc + col) = make_float2(v0, v1);
                } else {
                    if (EPI == 2) {
                        v0 = 0.5f*v0*(1.0f + erff(v0 * 0.70710678118654752f));
                        v1 = 0.5f*v1*(1.0f + erff(v1 * 0.70710678118654752f));
                    }
                    unsigned short h0, l0, h1, l1;
                    split1(v0, h0, l0); split1(v1, h1, l1);
                    const size_t ci = (size_t)r2*ldc + col;
                    *(ushort2*)(CH + ci) = make_ushort2(h0, h1);
                    *(ushort2*)(CL + ci) = make_ushort2(l0, l1);
                }
            }
        }
    }
}

// ---------------------------------------------------------------------------
// Fused flash attention fp16x2: Q split hi/lo, K/V hi only; P split hi/lo.
// 64-row KV tiles; smem 55 KB -> 2 CTAs/SM.
// ---------------------------------------------------------------------------
#define DPF 72
#define FLASH_SMEM ((2*128*DPF + 2*64*DPF) * 2)   // 55296 B

__global__ void __launch_bounds__(256, 2)
flash_attn(const __half* __restrict__ QKVH, const __half* __restrict__ QKVL,
           __half* __restrict__ OH, __half* __restrict__ OL)
{
    extern __shared__ __align__(16) unsigned short dynsm[];
    unsigned short* Qh = dynsm;
    unsigned short* Ql = Qh + 128*DPF;
    unsigned short* Kh = Ql + 128*DPF;
    unsigned short* Vh = Kh + 64*DPF;

    const int tid = threadIdx.x, lane = tid & 31, w = tid >> 5;
    const int b = blockIdx.y / NHH, hh = blockIdx.y % NHH;
    const int q0 = blockIdx.x * 128;
    const size_t qoff = ((size_t)b*SS + q0)*H3 + hh*DHH;
    const size_t koff = (size_t)b*SS*H3 + HH + hh*DHH;
    const size_t voff = (size_t)b*SS*H3 + 2*HH + hh*DHH;

    #pragma unroll
    for (int it = 0; it < 4; ++it) {
        int id = tid + it*256;
        int r = id >> 3, c8 = id & 7;
        *(uint4*)&Qh[r*DPF + c8*8] = *(const uint4*)(QKVH + qoff + (size_t)r*H3 + c8*8);
        *(uint4*)&Ql[r*DPF + c8*8] = *(const uint4*)(QKVL + qoff + (size_t)r*H3 + c8*8);
    }
    __syncthreads();

    float oacc[8][4] = {};
    float mrow[2] = {-1e30f, -1e30f};
    float lrow[2] = {0.0f, 0.0f};

    const int kb_row = (lane & 7) + ((lane & 16) >> 1);
    const int kb_col = ((lane >> 3) & 1) * 8;

    for (int j = 0; j < 8; ++j) {
        const size_t s0 = (size_t)j*64;
        #pragma unroll
        for (int it = 0; it < 2; ++it) {
            int id = tid + it*256;
            int r = id >> 3, c8 = id & 7;
            *(uint4*)&Kh[r*DPF + c8*8] = *(const uint4*)(QKVH + koff + (s0+r)*H3 + c8*8);
            *(uint4*)&Vh[r*DPF + c8*8] = *(const uint4*)(QKVH + voff + (s0+r)*H3 + c8*8);
        }
        __syncthreads();

        // --- S = Q K^T : 2 terms (Q full precision, K fp16) ---
        float sacc[8][4] = {};
        #pragma unroll
        for (int ks = 0; ks < 4; ++ks) {
            uint32_t qh[4], ql[4];
            int qr = w*16 + (lane & 15);
            int qc = ks*16 + ((lane >> 4) << 3);
            ldsm_x4(qh, smem_u32(Qh + qr*DPF + qc));
            ldsm_x4(ql, smem_u32(Ql + qr*DPF + qc));
            #pragma unroll
            for (int np = 0; np < 4; ++np) {
                uint32_t bh[4];
                int off = (np*16 + kb_row)*DPF + ks*16 + kb_col;
                ldsm_x4(bh, smem_u32(Kh + off));
                #pragma unroll
                for (int s = 0; s < 2; ++s) mma16816(sacc[np*2+s], qh, bh + s*2);
                #pragma unroll
                for (int s = 0; s < 2; ++s) mma16816(sacc[np*2+s], ql, bh + s*2);
            }
        }
        #pragma unroll
        for (int nt = 0; nt < 8; ++nt) {
            sacc[nt][0] *= 0.125f; sacc[nt][1] *= 0.125f;
            sacc[nt][2] *= 0.125f; sacc[nt][3] *= 0.125f;
        }

        // --- online softmax ---
        #pragma unroll
        for (int h = 0; h < 2; ++h) {
            float mx = -1e30f;
            #pragma unroll
            for (int nt = 0; nt < 8; ++nt)
                mx = fmaxf(mx, fmaxf(sacc[nt][2*h], sacc[nt][2*h+1]));
            mx = fmaxf(mx, __shfl_xor_sync(0xffffffffu, mx, 1));
            mx = fmaxf(mx, __shfl_xor_sync(0xffffffffu, mx, 2));
            float mnew = fmaxf(mrow[h], mx);
            float corr = expf(mrow[h] - mnew);
            mrow[h] = mnew;
            float sum = 0.0f;
            #pragma unroll
            for (int nt = 0; nt < 8; ++nt) {
                float p0 = expf(sacc[nt][2*h]   - mnew);
                float p1 = expf(sacc[nt][2*h+1] - mnew);
                sacc[nt][2*h] = p0; sacc[nt][2*h+1] = p1;
                sum += p0 + p1;
            }
            sum += __shfl_xor_sync(0xffffffffu, sum, 1);
            sum += __shfl_xor_sync(0xffffffffu, sum, 2);
            lrow[h] = lrow[h]*corr + sum;
            #pragma unroll
            for (int nt = 0; nt < 8; ++nt) {
                oacc[nt][2*h]   *= corr;
                oacc[nt][2*h+1] *= corr;
            }
        }

        // --- O += P V : 2 terms (P full precision, V fp16) ---
        #pragma unroll
        for (int ks = 0; ks < 4; ++ks) {
            uint32_t ph[4], pl[4];
            #pragma unroll
            for (int q = 0; q < 2; ++q) {
                #pragma unroll
                for (int hf = 0; hf < 2; ++hf) {
                    float x = sacc[2*ks+q][2*hf];
                    float y = sacc[2*ks+q][2*hf+1];
                    unsigned short hx, lx, hy, ly;
                    split1(x, hx, lx); split1(y, hy, ly);
                    ph[2*q+hf] = (uint32_t)hx | ((uint32_t)hy << 16);
                    pl[2*q+hf] = (uint32_t)lx | ((uint32_t)ly << 16);
                }
            }
            #pragma unroll
            for (int np = 0; np < 4; ++np) {
                uint32_t bh[4];
                int off = (ks*16 + (lane & 15))*DPF + np*16 + ((lane >> 4) << 3);
                ldsm_x4t(bh, smem_u32(Vh + off));
                #pragma unroll
                for (int s = 0; s < 2; ++s) mma16816(oacc[np*2+s], ph, bh + s*2);
                #pragma unroll
                for (int s = 0; s < 2; ++s) mma16816(oacc[np*2+s], pl, bh + s*2);
            }
        }
        __syncthreads();
    }

    const size_t obase = (size_t)b*SS*HH + (size_t)hh*DHH;
    const int orow = w*16 + (lane >> 2);
    #pragma unroll
    for (int h = 0; h < 2; ++h) {
        const float inv = 1.0f / lrow[h];
        const int r = q0 + orow + h*8;
        #pragma unroll
        for (int nt = 0; nt < 8; ++nt) {
            const int c = nt*8 + (lane & 3)*2;
            unsigned short h0, l0, h1, l1;
            split1(oacc[nt][2*h]*inv,   h0, l0);
            split1(oacc[nt][2*h+1]*inv, h1, l1);
            const size_t oi = obase + (size_t)r*HH + c;
            *(ushort2*)(OH + oi) = make_ushort2(h0, h1);
            *(ushort2*)(OL + oi) = make_ushort2(l0, l1);
        }
    }
}

// ---------------------------------------------------------------------------
// LayerNorm (warp per row). Sums X + X2 (split-K merge).
// SPLIT=1 -> fp16 hi/lo out; SPLIT=0 -> fp32 out.
// ---------------------------------------------------------------------------
template<int SPLIT>
__global__ void layernorm768(const float* __restrict__ X,
                             const float* __restrict__ X2,
                             const float* __restrict__ g,
                             const float* __restrict__ b,
                             float* __restrict__ Yf,
                             __half* __restrict__ YH,
                             __half* __restrict__ YL, int rows)
{
    const int warp = (blockIdx.x * blockDim.x + threadIdx.x) >> 5;
    const int lane = threadIdx.x & 31;
    if (warp >= rows) return;
    const float4* x  = (const float4*)(X  + (size_t)warp * 768);
    const float4* x2 = (const float4*)(X2 + (size_t)warp * 768);

    float4 v[6];
    float s = 0.0f;
    #pragma unroll
    for (int i = 0; i < 6; ++i) {
        float4 a = x[lane + i*32];
        float4 c = x2[lane + i*32];
        v[i] = make_float4(a.x + c.x, a.y + c.y, a.z + c.z, a.w + c.w);
        s += v[i].x + v[i].y + v[i].z + v[i].w;
    }
    #pragma unroll
    for (int o = 16; o; o >>= 1) s += __shfl_xor_sync(0xffffffffu, s, o);
    const float mean = s * (1.0f / 768.0f);

    float var = 0.0f;
    #pragma unroll
    for (int i = 0; i < 6; ++i) {
        float dx = v[i].x - mean, dy = v[i].y - mean, dz = v[i].z - mean, dw = v[i].w - mean;
        var += dx*dx + dy*dy + dz*dz + dw*dw;
    }
    #pragma unroll
    for (int o = 16; o; o >>= 1) var += __shfl_xor_sync(0xffffffffu, var, o);
    const float rs = rsqrtf(var * (1.0f / 768.0f) + 1e-12f);

    const float4* gg = (const float4*)g;
    const float4* bb = (const float4*)b;
    #pragma unroll
    for (int i = 0; i < 6; ++i) {
        const int c = lane + i*32;
        const float4 gv = gg[c], bv = bb[c];
        float4 o4;
        o4.x = (v[i].x - mean) * rs * gv.x + bv.x;
        o4.y = (v[i].y - mean) * rs * gv.y + bv.y;
        o4.z = (v[i].z - mean) * rs * gv.z + bv.z;
        o4.w = (v[i].w - mean) * rs * gv.w + bv.w;
        if (SPLIT) {
            ushort4 hi, lo; split4(o4, hi, lo);
            *(ushort4*)(YH + (size_t)warp*768 + c*4) = hi;
            *(ushort4*)(YL + (size_t)warp*768 + c*4) = lo;
        } else {
            *(float4*)(Yf + (size_t)warp*768 + c*4) = o4;
        }
    }
}

// ---------------------------------------------------------------------------
// Launch
// ---------------------------------------------------------------------------
extern "C" void kernel_launch(void* const* d_in, const int* in_sizes, int n_in,
                              void* d_out, int out_size)
{
    (void)in_sizes; (void)n_in; (void)out_size;
    const float* hs  = (const float*)d_in[0];
    const float* Wq  = (const float*)d_in[1];  const float* bq  = (const float*)d_in[2];
    const float* Wk  = (const float*)d_in[3];  const float* bk  = (const float*)d_in[4];
    const float* Wv  = (const float*)d_in[5];  const float* bv  = (const float*)d_in[6];
    const float* Wo  = (const float*)d_in[7];  const float* bo  = (const float*)d_in[8];
    const float* g1  = (const float*)d_in[9];  const float* b1  = (const float*)d_in[10];
    const float* Wi  = (const float*)d_in[11]; const float* bi  = (const float*)d_in[12];
    const float* Wo2 = (const float*)d_in[13]; const float* bo2 = (const float*)d_in[14];
    const float* g2  = (const float*)d_in[15]; const float* b2  = (const float*)d_in[16];

    __half *XH, *XL, *QKVH, *QKVL, *CH, *CL, *AH, *AL, *IH, *IL;
    __half *Wqkv, *WoD, *WiD, *Wo2D;
    float *T, *T2, *bqkv;
    cudaGetSymbolAddress((void**)&XH, g_XH);   cudaGetSymbolAddress((void**)&XL, g_XL);
    cudaGetSymbolAddress((void**)&QKVH, g_QKVH); cudaGetSymbolAddress((void**)&QKVL, g_QKVL);
    cudaGetSymbolAddress((void**)&CH, g_CH);   cudaGetSymbolAddress((void**)&CL, g_CL);
    cudaGetSymbolAddress((void**)&AH, g_AH);   cudaGetSymbolAddress((void**)&AL, g_AL);
    cudaGetSymbolAddress((void**)&IH, g_IH);   cudaGetSymbolAddress((void**)&IL, g_IL);
    cudaGetSymbolAddress((void**)&T,  g_T);    cudaGetSymbolAddress((void**)&T2, g_T2);
    cudaGetSymbolAddress((void**)&bqkv, g_bqkv);
    cudaGetSymbolAddress((void**)&Wqkv, g_Wqkv);
    cudaGetSymbolAddress((void**)&WoD,  g_Wo);
    cudaGetSymbolAddress((void**)&WiD,  g_Wi);
    cudaGetSymbolAddress((void**)&Wo2D, g_Wo2);

    cudaFuncSetAttribute((const void*)gemm_cp<0,0>, cudaFuncAttributeMaxDynamicSharedMemorySize, GEMM_SMEM);
    cudaFuncSetAttribute((const void*)gemm_cp<1,1>, cudaFuncAttributeMaxDynamicSharedMemorySize, GEMM_SMEM);
    cudaFuncSetAttribute((const void*)gemm_cp<2,0>, cudaFuncAttributeMaxDynamicSharedMemorySize, GEMM_SMEM);
    cudaFuncSetAttribute((const void*)flash_attn, cudaFuncAttributeMaxDynamicSharedMemorySize, FLASH_SMEM);

    // --- preprocessing ---
    split_all<<<dim3(HH*II/1024, LL, 6), 256>>>(Wq, Wk, Wv, Wo, Wi, Wo2,
        Wqkv, WoD, WiD, Wo2D);
    concat_bias<<<(LL*HH + 255)/256, 256>>>(bq, bk, bv, bqkv);
    split_x<<<(M0*HH/4 + 255)/256, 256>>>(hs, XH, XL, M0*HH/4);

    for (int l = 0; l < LL; ++l) {
        const __half* wqkv = Wqkv + (size_t)l*HH*H3;
        const __half* wo   = WoD  + (size_t)l*HH*HH;
        const __half* wi   = WiD  + (size_t)l*HH*II;
        const __half* wo2  = Wo2D + (size_t)l*II*HH;
        const float* bqkvl = bqkv + (size_t)l*H3;
        const float* bol   = bo   + (size_t)l*HH;
        const float* bil   = bi   + (size_t)l*II;
        const float* bo2l  = bo2  + (size_t)l*HH;

        // QKV projection (2304 CTAs of 64x128)
        gemm_cp<0,0><<<dim3(H3/128, M0/64), 256, GEMM_SMEM>>>(
            XH, XL, HH, wqkv, H3, bqkvl,
            nullptr, nullptr, 0, nullptr, nullptr, QKVH, QKVL, H3, HH);

        // fused attention -> ctx (hi/lo)
        flash_attn<<<dim3(SS/128, NBA), 256, FLASH_SMEM>>>(QKVH, QKVL, CH, CL);

        // O projection + residual(X): split-K=2 (1536 CTAs of K=384)
        gemm_cp<1,1><<<dim3(HH/128, M0/64, 2), 256, GEMM_SMEM>>>(
            CH, CL, HH, wo, HH, bol,
            XH, XL, HH, T, T2, nullptr, nullptr, HH, HH/2);
        layernorm768<1><<<M0/8, 256>>>(T, T2, g1 + (size_t)l*HH, b1 + (size_t)l*HH,
                                       nullptr, AH, AL, M0);

        // FFN1: I = gelu(A @ Wi + bi)  (3072 CTAs)
        gemm_cp<2,0><<<dim3(II/128, M0/64), 256, GEMM_SMEM>>>(
            AH, AL, HH, wi, II, bil,
            nullptr, nullptr, 0, nullptr, nullptr, IH, IL, II, HH);

        // FFN2 + residual(A): split-K=2 (1536 CTAs of K=1536)
        gemm_cp<1,1><<<dim3(HH/128, M0/64, 2), 256, GEMM_SMEM>>>(
            IH, IL, II, wo2, HH, bo2l,
            AH, AL, HH, T, T2, nullptr, nullptr, HH, II/2);

        if (l == LL-1) {
            layernorm768<0><<<M0/8, 256>>>(T, T2, g2 + (size_t)l*HH, b2 + (size_t)l*HH,
                                           (float*)d_out, nullptr, nullptr, M0);
        } else {
            layernorm768<1><<<M0/8, 256>>>(T, T2, g2 + (size_t)l*HH, b2 + (size_t)l*HH,
                                           nullptr, XH, XL, M0);
        }
    }
}

// round 16
// speedup vs baseline: 1.6007x; 1.0580x over previous
#include <cuda_runtime.h>
#include <cuda_fp16.h>
#include <math.h>
#include <stdint.h>

// Problem constants
#define BB   16
#define SS   512
#define HH   768
#define II   3072
#define NHH  12
#define DHH  64
#define LL   6
#define M0   (BB*SS)       // 8192 tokens
#define NBA  (BB*NHH)      // 192 attention batches
#define H3   (3*HH)        // 2304

// ---------------------------------------------------------------------------
// Scratch buffers. Activations: fp16 hi/lo pairs. Weights: fp16 (hi only).
// ---------------------------------------------------------------------------
__device__ __half g_XH[M0*HH],   g_XL[M0*HH];
__device__ __half g_QKVH[M0*H3], g_QKVL[M0*H3];
__device__ __half g_CH[M0*HH],   g_CL[M0*HH];
__device__ __half g_AH[M0*HH],   g_AL[M0*HH];
__device__ __half g_IH[M0*II],   g_IL[M0*II];
__device__ float g_T[M0*HH];
__device__ float g_T2[M0*HH];
__device__ __half g_Wqkv[LL*HH*H3];
__device__ __half g_Wo[LL*HH*HH];
__device__ __half g_Wi[LL*HH*II];
__device__ __half g_Wo2[LL*II*HH];
__device__ float g_bqkv[LL*H3];

// ---------------------------------------------------------------------------
// PTX helpers
// ---------------------------------------------------------------------------
__device__ __forceinline__ uint32_t smem_u32(const void* p) {
    return (uint32_t)__cvta_generic_to_shared(p);
}
__device__ __forceinline__ void ldsm_x4(uint32_t* r, uint32_t a) {
    asm volatile("ldmatrix.sync.aligned.m8n8.x4.shared.b16 {%0,%1,%2,%3}, [%4];"
        : "=r"(r[0]), "=r"(r[1]), "=r"(r[2]), "=r"(r[3]) : "r"(a));
}
__device__ __forceinline__ void ldsm_x4t(uint32_t* r, uint32_t a) {
    asm volatile("ldmatrix.sync.aligned.m8n8.x4.trans.shared.b16 {%0,%1,%2,%3}, [%4];"
        : "=r"(r[0]), "=r"(r[1]), "=r"(r[2]), "=r"(r[3]) : "r"(a));
}
__device__ __forceinline__ void mma16816(float* c, const uint32_t* a, const uint32_t* b) {
    asm volatile(
        "mma.sync.aligned.m16n8k16.row.col.f32.f16.f16.f32 "
        "{%0,%1,%2,%3}, {%4,%5,%6,%7}, {%8,%9}, {%0,%1,%2,%3};"
        : "+f"(c[0]), "+f"(c[1]), "+f"(c[2]), "+f"(c[3])
        : "r"(a[0]), "r"(a[1]), "r"(a[2]), "r"(a[3]), "r"(b[0]), "r"(b[1]));
}
#define CP_ASYNC16(dst, src) \
    asm volatile("cp.async.cg.shared.global [%0], [%1], 16;" :: "r"(dst), "l"(src) : "memory")
#define CP_COMMIT() asm volatile("cp.async.commit_group;" ::: "memory")
#define CP_WAIT1()  asm volatile("cp.async.wait_group 1;" ::: "memory")

// fp32 -> (fp16 hi, fp16 lo) residual split
__device__ __forceinline__ void split1(float x, unsigned short& hi, unsigned short& lo) {
    __half h = __float2half(x);
    hi = __half_as_ushort(h);
    float r = x - __half2float(h);
    lo = __half_as_ushort(__float2half(r));
}
__device__ __forceinline__ void split4(float4 v, ushort4& hi, ushort4& lo) {
    split1(v.x, hi.x, lo.x);
    split1(v.y, hi.y, lo.y);
    split1(v.z, hi.z, lo.z);
    split1(v.w, hi.w, lo.w);
}
__device__ __forceinline__ float h2f(unsigned short u) {
    return __half2float(__ushort_as_half(u));
}

// ---------------------------------------------------------------------------
// Preprocessing: weights -> fp16
// ---------------------------------------------------------------------------
__global__ void split_all(const float* __restrict__ Wq, const float* __restrict__ Wk,
                          const float* __restrict__ Wv, const float* __restrict__ Wo,
                          const float* __restrict__ Wi, const float* __restrict__ Wo2,
                          __half* __restrict__ Wqkv, __half* __restrict__ WoD,
                          __half* __restrict__ WiD,  __half* __restrict__ Wo2D)
{
    const int l = blockIdx.y;
    const float* src; __half* dh;
    int R, Cc, outC, colOff;
    switch (blockIdx.z) {
        case 0: src = Wq;  dh = Wqkv; R = HH; Cc = HH; outC = H3; colOff = 0;    break;
        case 1: src = Wk;  dh = Wqkv; R = HH; Cc = HH; outC = H3; colOff = HH;   break;
        case 2: src = Wv;  dh = Wqkv; R = HH; Cc = HH; outC = H3; colOff = 2*HH; break;
        case 3: src = Wo;  dh = WoD;  R = HH; Cc = HH; outC = HH; colOff = 0;    break;
        case 4: src = Wi;  dh = WiD;  R = HH; Cc = II; outC = II; colOff = 0;    break;
        default:src = Wo2; dh = Wo2D; R = II; Cc = HH; outC = HH; colOff = 0;    break;
    }
    int id = blockIdx.x*256 + threadIdx.x;
    if (id >= R*Cc/4) return;
    int r = id / (Cc/4), c4 = id % (Cc/4);
    float4 v = *(const float4*)(src + (size_t)l*R*Cc + (size_t)r*Cc + c4*4);
    ushort4 hi;
    hi.x = __half_as_ushort(__float2half(v.x));
    hi.y = __half_as_ushort(__float2half(v.y));
    hi.z = __half_as_ushort(__float2half(v.z));
    hi.w = __half_as_ushort(__float2half(v.w));
    *(ushort4*)(dh + (size_t)l*R*outC + (size_t)r*outC + colOff + c4*4) = hi;
}

__global__ void concat_bias(const float* __restrict__ bq, const float* __restrict__ bk,
                            const float* __restrict__ bv, float* __restrict__ dst)
{
    int id = blockIdx.x*256 + threadIdx.x;
    if (id >= LL*HH) return;
    int l = id / HH, c = id % HH;
    dst[(size_t)l*H3 + c]        = bq[id];
    dst[(size_t)l*H3 + HH + c]   = bk[id];
    dst[(size_t)l*H3 + 2*HH + c] = bv[id];
}

__global__ void split_x(const float* __restrict__ src,
                        __half* __restrict__ dh, __half* __restrict__ dl, int n4)
{
    int id = blockIdx.x*256 + threadIdx.x;
    if (id >= n4) return;
    float4 v = *(const float4*)(src + (size_t)id*4);
    ushort4 hi, lo; split4(v, hi, lo);
    *(ushort4*)(dh + (size_t)id*4) = hi;
    *(ushort4*)(dl + (size_t)id*4) = lo;
}

// ---------------------------------------------------------------------------
// fp16x2 GEMM v3: block 64x128x16, FOUR warps (warp tile 32x64, grid 2x2),
// minimizing smem-read redundancy (A x2, B x2 = 0.061 B/MAC).
// 3-stage cp.async, 4 CTAs/SM (16 warps).
// SPLITK: gridDim.z=2; z=0 -> EPI into Cf, z=1 -> raw partial into Cf2.
// EPI: 0 = bias -> split out; 1 = bias + residual -> fp32; 2 = bias+GELU -> split
// ---------------------------------------------------------------------------
#define LAS   24            // A row stride (shorts): 16 + 8 pad
#define LBS   136           // B row stride (shorts): 128 + 8 pad
#define ASZ   (64*LAS)      // 1536 shorts
#define BSZ   (16*LBS)      // 2176 shorts
#define STG   (2*ASZ + BSZ)            // 5248 shorts = 10496 B
#define GEMM_SMEM (3*STG*2)            // 31488 B

template<int EPI, int SPLITK>
__global__ void __launch_bounds__(128, 4)
gemm_cp(const __half* __restrict__ AH, const __half* __restrict__ AL, int lda,
        const __half* __restrict__ B, int ldb,
        const float* __restrict__ bias,
        const __half* __restrict__ RH, const __half* __restrict__ RL, int ldr,
        float* __restrict__ Cf, float* __restrict__ Cf2,
        __half* __restrict__ CH, __half* __restrict__ CL,
        int ldc, int K)
{
    extern __shared__ __align__(16) unsigned short sm[];
    const uint32_t smb = smem_u32(sm);

    const int tid = threadIdx.x, lane = tid & 31, wid = tid >> 5;
    const int wm = wid >> 1, wn = wid & 1;          // 2x2 warp grid, tile 32x64
    const int m0 = blockIdx.y * 64, n0 = blockIdx.x * 128;

    if (SPLITK) {
        const size_t koff = (size_t)blockIdx.z * K;
        AH += koff; AL += koff;
        B  += koff * ldb;
    }

    float acc[2][8][4] = {};

    auto issue = [&](int st, int k0) {
        const uint32_t base = smb + st*STG*2;
        // A: 64 rows x 2 chunks = 128 per matrix -> 1 hi + 1 lo per thread
        {
            int ar = tid >> 1, ac = tid & 1;
            uint32_t d = base + (uint32_t)(ar*LAS + ac*8)*2;
            const size_t off = (size_t)(m0+ar)*lda + k0 + ac*8;
            CP_ASYNC16(d,         AH + off);
            CP_ASYNC16(d + ASZ*2, AL + off);
        }
        // B: 16 rows x 16 chunks = 256 -> 2 per thread
        #pragma unroll
        for (int it = 0; it < 2; ++it) {
            int id = tid + it*128;
            int r = id >> 4, cc = id & 15;
            uint32_t d = base + 2*ASZ*2 + (uint32_t)(r*LBS + cc*8)*2;
            CP_ASYNC16(d, B + (size_t)(k0+r)*ldb + n0 + cc*8);
        }
    };

    const int nk = K / 16;
    issue(0, 0);  CP_COMMIT();
    issue(1, 16); CP_COMMIT();

    for (int kt = 0; kt < nk; ++kt) {
        CP_WAIT1();
        __syncthreads();
        if (kt + 2 < nk) issue((kt+2) % 3, (kt+2)*16);
        CP_COMMIT();

        const unsigned short* Ah = sm + (kt % 3)*STG;
        const unsigned short* Al = Ah + ASZ;
        const unsigned short* Bh = Al + ASZ;

        uint32_t ah[2][4], al[2][4];
        #pragma unroll
        for (int mt = 0; mt < 2; ++mt) {
            int r = wm*32 + mt*16 + (lane & 15);
            int c = (lane >> 4) << 3;
            ldsm_x4(ah[mt], smem_u32(Ah + r*LAS + c));
            ldsm_x4(al[mt], smem_u32(Al + r*LAS + c));
        }
        #pragma unroll
        for (int np = 0; np < 4; ++np) {
            uint32_t bh[4];
            int off = (lane & 15)*LBS + wn*64 + np*16 + ((lane >> 4) << 3);
            ldsm_x4t(bh, smem_u32(Bh + off));
            #pragma unroll
            for (int s = 0; s < 2; ++s)
                #pragma unroll
                for (int mt = 0; mt < 2; ++mt)
                    mma16816(acc[mt][np*2+s], ah[mt], bh + s*2);
            #pragma unroll
            for (int s = 0; s < 2; ++s)
                #pragma unroll
                for (int mt = 0; mt < 2; ++mt)
                    mma16816(acc[mt][np*2+s], al[mt], bh + s*2);
        }
    }

    // --- epilogue ---
    const bool plain = SPLITK && (blockIdx.z == 1);
    #pragma unroll
    for (int mt = 0; mt < 2; ++mt) {
        #pragma unroll
        for (int nt = 0; nt < 8; ++nt) {
            const int row = m0 + wm*32 + mt*16 + (lane >> 2);
            const int col = n0 + wn*64 + nt*8 + (lane & 3)*2;
            #pragma unroll
            for (int h = 0; h < 2; ++h) {
                const int r2 = row + h*8;
                float v0 = acc[mt][nt][h*2+0];
                float v1 = acc[mt][nt][h*2+1];
                if (plain) {
                    *(float2*)(Cf2 + (size_t)r2*ldc + col) = make_float2(v0, v1);
                    continue;
                }
                v0 += bias[col]; v1 += bias[col+1];
                if (EPI == 1) {
                    const size_t ri = (size_t)r2*ldr + col;
                    const ushort2 rh = *(const ushort2*)(RH + ri);
                    const ushort2 rl = *(const ushort2*)(RL + ri);
                    v0 += h2f(rh.x) + h2f(rl.x);
                    v1 += h2f(rh.y) + h2f(rl.y);
                    *(float2*)(Cf + (size_t)r2*ldc + col) = make_float2(v0, v1);
                } else {
                    if (EPI == 2) {
                        v0 = 0.5f*v0*(1.0f + erff(v0 * 0.70710678118654752f));
                        v1 = 0.5f*v1*(1.0f + erff(v1 * 0.70710678118654752f));
                    }
                    unsigned short h0, l0, h1, l1;
                    split1(v0, h0, l0); split1(v1, h1, l1);
                    const size_t ci = (size_t)r2*ldc + col;
                    *(ushort2*)(CH + ci) = make_ushort2(h0, h1);
                    *(ushort2*)(CL + ci) = make_ushort2(l0, l1);
                }
            }
        }
    }
}

// ---------------------------------------------------------------------------
// Fused flash attention fp16x2: Q split hi/lo, K/V hi only; P split hi/lo.
// 64-row KV tiles; smem 55 KB -> 2 CTAs/SM. (unchanged from R15)
// ---------------------------------------------------------------------------
#define DPF 72
#define FLASH_SMEM ((2*128*DPF + 2*64*DPF) * 2)   // 55296 B

__global__ void __launch_bounds__(256, 2)
flash_attn(const __half* __restrict__ QKVH, const __half* __restrict__ QKVL,
           __half* __restrict__ OH, __half* __restrict__ OL)
{
    extern __shared__ __align__(16) unsigned short dynsm[];
    unsigned short* Qh = dynsm;
    unsigned short* Ql = Qh + 128*DPF;
    unsigned short* Kh = Ql + 128*DPF;
    unsigned short* Vh = Kh + 64*DPF;

    const int tid = threadIdx.x, lane = tid & 31, w = tid >> 5;
    const int b = blockIdx.y / NHH, hh = blockIdx.y % NHH;
    const int q0 = blockIdx.x * 128;
    const size_t qoff = ((size_t)b*SS + q0)*H3 + hh*DHH;
    const size_t koff = (size_t)b*SS*H3 + HH + hh*DHH;
    const size_t voff = (size_t)b*SS*H3 + 2*HH + hh*DHH;

    #pragma unroll
    for (int it = 0; it < 4; ++it) {
        int id = tid + it*256;
        int r = id >> 3, c8 = id & 7;
        *(uint4*)&Qh[r*DPF + c8*8] = *(const uint4*)(QKVH + qoff + (size_t)r*H3 + c8*8);
        *(uint4*)&Ql[r*DPF + c8*8] = *(const uint4*)(QKVL + qoff + (size_t)r*H3 + c8*8);
    }
    __syncthreads();

    float oacc[8][4] = {};
    float mrow[2] = {-1e30f, -1e30f};
    float lrow[2] = {0.0f, 0.0f};

    const int kb_row = (lane & 7) + ((lane & 16) >> 1);
    const int kb_col = ((lane >> 3) & 1) * 8;

    for (int j = 0; j < 8; ++j) {
        const size_t s0 = (size_t)j*64;
        #pragma unroll
        for (int it = 0; it < 2; ++it) {
            int id = tid + it*256;
            int r = id >> 3, c8 = id & 7;
            *(uint4*)&Kh[r*DPF + c8*8] = *(const uint4*)(QKVH + koff + (s0+r)*H3 + c8*8);
            *(uint4*)&Vh[r*DPF + c8*8] = *(const uint4*)(QKVH + voff + (s0+r)*H3 + c8*8);
        }
        __syncthreads();

        float sacc[8][4] = {};
        #pragma unroll
        for (int ks = 0; ks < 4; ++ks) {
            uint32_t qh[4], ql[4];
            int qr = w*16 + (lane & 15);
            int qc = ks*16 + ((lane >> 4) << 3);
            ldsm_x4(qh, smem_u32(Qh + qr*DPF + qc));
            ldsm_x4(ql, smem_u32(Ql + qr*DPF + qc));
            #pragma unroll
            for (int np = 0; np < 4; ++np) {
                uint32_t bh[4];
                int off = (np*16 + kb_row)*DPF + ks*16 + kb_col;
                ldsm_x4(bh, smem_u32(Kh + off));
                #pragma unroll
                for (int s = 0; s < 2; ++s) mma16816(sacc[np*2+s], qh, bh + s*2);
                #pragma unroll
                for (int s = 0; s < 2; ++s) mma16816(sacc[np*2+s], ql, bh + s*2);
            }
        }
        #pragma unroll
        for (int nt = 0; nt < 8; ++nt) {
            sacc[nt][0] *= 0.125f; sacc[nt][1] *= 0.125f;
            sacc[nt][2] *= 0.125f; sacc[nt][3] *= 0.125f;
        }

        #pragma unroll
        for (int h = 0; h < 2; ++h) {
            float mx = -1e30f;
            #pragma unroll
            for (int nt = 0; nt < 8; ++nt)
                mx = fmaxf(mx, fmaxf(sacc[nt][2*h], sacc[nt][2*h+1]));
            mx = fmaxf(mx, __shfl_xor_sync(0xffffffffu, mx, 1));
            mx = fmaxf(mx, __shfl_xor_sync(0xffffffffu, mx, 2));
            float mnew = fmaxf(mrow[h], mx);
            float corr = expf(mrow[h] - mnew);
            mrow[h] = mnew;
            float sum = 0.0f;
            #pragma unroll
            for (int nt = 0; nt < 8; ++nt) {
                float p0 = expf(sacc[nt][2*h]   - mnew);
                float p1 = expf(sacc[nt][2*h+1] - mnew);
                sacc[nt][2*h] = p0; sacc[nt][2*h+1] = p1;
                sum += p0 + p1;
            }
            sum += __shfl_xor_sync(0xffffffffu, sum, 1);
            sum += __shfl_xor_sync(0xffffffffu, sum, 2);
            lrow[h] = lrow[h]*corr + sum;
            #pragma unroll
            for (int nt = 0; nt < 8; ++nt) {
                oacc[nt][2*h]   *= corr;
                oacc[nt][2*h+1] *= corr;
            }
        }

        #pragma unroll
        for (int ks = 0; ks < 4; ++ks) {
            uint32_t ph[4], pl[4];
            #pragma unroll
            for (int q = 0; q < 2; ++q) {
                #pragma unroll
                for (int hf = 0; hf < 2; ++hf) {
                    float x = sacc[2*ks+q][2*hf];
                    float y = sacc[2*ks+q][2*hf+1];
                    unsigned short hx, lx, hy, ly;
                    split1(x, hx, lx); split1(y, hy, ly);
                    ph[2*q+hf] = (uint32_t)hx | ((uint32_t)hy << 16);
                    pl[2*q+hf] = (uint32_t)lx | ((uint32_t)ly << 16);
                }
            }
            #pragma unroll
            for (int np = 0; np < 4; ++np) {
                uint32_t bh[4];
                int off = (ks*16 + (lane & 15))*DPF + np*16 + ((lane >> 4) << 3);
                ldsm_x4t(bh, smem_u32(Vh + off));
                #pragma unroll
                for (int s = 0; s < 2; ++s) mma16816(oacc[np*2+s], ph, bh + s*2);
                #pragma unroll
                for (int s = 0; s < 2; ++s) mma16816(oacc[np*2+s], pl, bh + s*2);
            }
        }
        __syncthreads();
    }

    const size_t obase = (size_t)b*SS*HH + (size_t)hh*DHH;
    const int orow = w*16 + (lane >> 2);
    #pragma unroll
    for (int h = 0; h < 2; ++h) {
        const float inv = 1.0f / lrow[h];
        const int r = q0 + orow + h*8;
        #pragma unroll
        for (int nt = 0; nt < 8; ++nt) {
            const int c = nt*8 + (lane & 3)*2;
            unsigned short h0, l0, h1, l1;
            split1(oacc[nt][2*h]*inv,   h0, l0);
            split1(oacc[nt][2*h+1]*inv, h1, l1);
            const size_t oi = obase + (size_t)r*HH + c;
            *(ushort2*)(OH + oi) = make_ushort2(h0, h1);
            *(ushort2*)(OL + oi) = make_ushort2(l0, l1);
        }
    }
}

// ---------------------------------------------------------------------------
// LayerNorm (warp per row). Sums X + X2 (split-K merge).
// SPLIT=1 -> fp16 hi/lo out; SPLIT=0 -> fp32 out.
// ---------------------------------------------------------------------------
template<int SPLIT>
__global__ void layernorm768(const float* __restrict__ X,
                             const float* __restrict__ X2,
                             const float* __restrict__ g,
                             const float* __restrict__ b,
                             float* __restrict__ Yf,
                             __half* __restrict__ YH,
                             __half* __restrict__ YL, int rows)
{
    const int warp = (blockIdx.x * blockDim.x + threadIdx.x) >> 5;
    const int lane = threadIdx.x & 31;
    if (warp >= rows) return;
    const float4* x  = (const float4*)(X  + (size_t)warp * 768);
    const float4* x2 = (const float4*)(X2 + (size_t)warp * 768);

    float4 v[6];
    float s = 0.0f;
    #pragma unroll
    for (int i = 0; i < 6; ++i) {
        float4 a = x[lane + i*32];
        float4 c = x2[lane + i*32];
        v[i] = make_float4(a.x + c.x, a.y + c.y, a.z + c.z, a.w + c.w);
        s += v[i].x + v[i].y + v[i].z + v[i].w;
    }
    #pragma unroll
    for (int o = 16; o; o >>= 1) s += __shfl_xor_sync(0xffffffffu, s, o);
    const float mean = s * (1.0f / 768.0f);

    float var = 0.0f;
    #pragma unroll
    for (int i = 0; i < 6; ++i) {
        float dx = v[i].x - mean, dy = v[i].y - mean, dz = v[i].z - mean, dw = v[i].w - mean;
        var += dx*dx + dy*dy + dz*dz + dw*dw;
    }
    #pragma unroll
    for (int o = 16; o; o >>= 1) var += __shfl_xor_sync(0xffffffffu, var, o);
    const float rs = rsqrtf(var * (1.0f / 768.0f) + 1e-12f);

    const float4* gg = (const float4*)g;
    const float4* bb = (const float4*)b;
    #pragma unroll
    for (int i = 0; i < 6; ++i) {
        const int c = lane + i*32;
        const float4 gv = gg[c], bv = bb[c];
        float4 o4;
        o4.x = (v[i].x - mean) * rs * gv.x + bv.x;
        o4.y = (v[i].y - mean) * rs * gv.y + bv.y;
        o4.z = (v[i].z - mean) * rs * gv.z + bv.z;
        o4.w = (v[i].w - mean) * rs * gv.w + bv.w;
        if (SPLIT) {
            ushort4 hi, lo; split4(o4, hi, lo);
            *(ushort4*)(YH + (size_t)warp*768 + c*4) = hi;
            *(ushort4*)(YL + (size_t)warp*768 + c*4) = lo;
        } else {
            *(float4*)(Yf + (size_t)warp*768 + c*4) = o4;
        }
    }
}

// ---------------------------------------------------------------------------
// Launch
// ---------------------------------------------------------------------------
extern "C" void kernel_launch(void* const* d_in, const int* in_sizes, int n_in,
                              void* d_out, int out_size)
{
    (void)in_sizes; (void)n_in; (void)out_size;
    const float* hs  = (const float*)d_in[0];
    const float* Wq  = (const float*)d_in[1];  const float* bq  = (const float*)d_in[2];
    const float* Wk  = (const float*)d_in[3];  const float* bk  = (const float*)d_in[4];
    const float* Wv  = (const float*)d_in[5];  const float* bv  = (const float*)d_in[6];
    const float* Wo  = (const float*)d_in[7];  const float* bo  = (const float*)d_in[8];
    const float* g1  = (const float*)d_in[9];  const float* b1  = (const float*)d_in[10];
    const float* Wi  = (const float*)d_in[11]; const float* bi  = (const float*)d_in[12];
    const float* Wo2 = (const float*)d_in[13]; const float* bo2 = (const float*)d_in[14];
    const float* g2  = (const float*)d_in[15]; const float* b2  = (const float*)d_in[16];

    __half *XH, *XL, *QKVH, *QKVL, *CH, *CL, *AH, *AL, *IH, *IL;
    __half *Wqkv, *WoD, *WiD, *Wo2D;
    float *T, *T2, *bqkv;
    cudaGetSymbolAddress((void**)&XH, g_XH);   cudaGetSymbolAddress((void**)&XL, g_XL);
    cudaGetSymbolAddress((void**)&QKVH, g_QKVH); cudaGetSymbolAddress((void**)&QKVL, g_QKVL);
    cudaGetSymbolAddress((void**)&CH, g_CH);   cudaGetSymbolAddress((void**)&CL, g_CL);
    cudaGetSymbolAddress((void**)&AH, g_AH);   cudaGetSymbolAddress((void**)&AL, g_AL);
    cudaGetSymbolAddress((void**)&IH, g_IH);   cudaGetSymbolAddress((void**)&IL, g_IL);
    cudaGetSymbolAddress((void**)&T,  g_T);    cudaGetSymbolAddress((void**)&T2, g_T2);
    cudaGetSymbolAddress((void**)&bqkv, g_bqkv);
    cudaGetSymbolAddress((void**)&Wqkv, g_Wqkv);
    cudaGetSymbolAddress((void**)&WoD,  g_Wo);
    cudaGetSymbolAddress((void**)&WiD,  g_Wi);
    cudaGetSymbolAddress((void**)&Wo2D, g_Wo2);

    cudaFuncSetAttribute((const void*)gemm_cp<0,0>, cudaFuncAttributeMaxDynamicSharedMemorySize, GEMM_SMEM);
    cudaFuncSetAttribute((const void*)gemm_cp<1,1>, cudaFuncAttributeMaxDynamicSharedMemorySize, GEMM_SMEM);
    cudaFuncSetAttribute((const void*)gemm_cp<2,0>, cudaFuncAttributeMaxDynamicSharedMemorySize, GEMM_SMEM);
    cudaFuncSetAttribute((const void*)flash_attn, cudaFuncAttributeMaxDynamicSharedMemorySize, FLASH_SMEM);

    // --- preprocessing ---
    split_all<<<dim3(HH*II/1024, LL, 6), 256>>>(Wq, Wk, Wv, Wo, Wi, Wo2,
        Wqkv, WoD, WiD, Wo2D);
    concat_bias<<<(LL*HH + 255)/256, 256>>>(bq, bk, bv, bqkv);
    split_x<<<(M0*HH/4 + 255)/256, 256>>>(hs, XH, XL, M0*HH/4);

    for (int l = 0; l < LL; ++l) {
        const __half* wqkv = Wqkv + (size_t)l*HH*H3;
        const __half* wo   = WoD  + (size_t)l*HH*HH;
        const __half* wi   = WiD  + (size_t)l*HH*II;
        const __half* wo2  = Wo2D + (size_t)l*II*HH;
        const float* bqkvl = bqkv + (size_t)l*H3;
        const float* bol   = bo   + (size_t)l*HH;
        const float* bil   = bi   + (size_t)l*II;
        const float* bo2l  = bo2  + (size_t)l*HH;

        // QKV projection (2304 CTAs of 64x128, 128 threads)
        gemm_cp<0,0><<<dim3(H3/128, M0/64), 128, GEMM_SMEM>>>(
            XH, XL, HH, wqkv, H3, bqkvl,
            nullptr, nullptr, 0, nullptr, nullptr, QKVH, QKVL, H3, HH);

        // fused attention -> ctx (hi/lo)
        flash_attn<<<dim3(SS/128, NBA), 256, FLASH_SMEM>>>(QKVH, QKVL, CH, CL);

        // O projection + residual(X): split-K=2 (1536 CTAs of K=384)
        gemm_cp<1,1><<<dim3(HH/128, M0/64, 2), 128, GEMM_SMEM>>>(
            CH, CL, HH, wo, HH, bol,
            XH, XL, HH, T, T2, nullptr, nullptr, HH, HH/2);
        layernorm768<1><<<M0/8, 256>>>(T, T2, g1 + (size_t)l*HH, b1 + (size_t)l*HH,
                                       nullptr, AH, AL, M0);

        // FFN1: I = gelu(A @ Wi + bi)  (3072 CTAs)
        gemm_cp<2,0><<<dim3(II/128, M0/64), 128, GEMM_SMEM>>>(
            AH, AL, HH, wi, II, bil,
            nullptr, nullptr, 0, nullptr, nullptr, IH, IL, II, HH);

        // FFN2 + residual(A): split-K=2 (1536 CTAs of K=1536)
        gemm_cp<1,1><<<dim3(HH/128, M0/64, 2), 128, GEMM_SMEM>>>(
            IH, IL, II, wo2, HH, bo2l,
            AH, AL, HH, T, T2, nullptr, nullptr, HH, II/2);

        if (l == LL-1) {
            layernorm768<0><<<M0/8, 256>>>(T, T2, g2 + (size_t)l*HH, b2 + (size_t)l*HH,
                                           (float*)d_out, nullptr, nullptr, M0);
        } else {
            layernorm768<1><<<M0/8, 256>>>(T, T2, g2 + (size_t)l*HH, b2 + (size_t)l*HH,
                                           nullptr, XH, XL, M0);
        }
    }
}